// round 3
// baseline (speedup 1.0000x reference)
#include <cuda_runtime.h>
#include <math_constants.h>

// Problem shape (fixed for this registry entry)
#define B_  8
#define N_  2048
#define C_  64
#define H_  4
#define D_  64
#define HD_ 256          // H*D
#define NW_ (N_/32)      // mask words per row = 64
#define LOG2E 1.4426950408889634f

typedef unsigned long long ull;

// ---------------- scratch (device globals: no allocation allowed) -----------
__device__ float    g_h  [B_*H_*N_*D_];   // 16 MB  per-head projected features
__device__ float    g_z  [B_*N_*HD_];     // 16 MB  concat+lrelu of layer-1 output
__device__ float    g_h2 [B_*N_*D_];      //  4 MB  second projection
__device__ unsigned g_maskT[NW_*N_];      // 512 KB transposed bitmask [w][n]

// ---------------- packed f32x2 helpers ---------------------------------------
__device__ __forceinline__ ull fma2(ull a, ull b, ull c) {
    ull d;
    asm("fma.rn.f32x2 %0, %1, %2, %3;" : "=l"(d) : "l"(a), "l"(b), "l"(c));
    return d;
}
__device__ __forceinline__ ull pk2(float lo, float hi) {
    ull r;
    asm("mov.b64 %0, {%1, %2};" : "=l"(r) : "f"(lo), "f"(hi));
    return r;
}
__device__ __forceinline__ void upk2(ull v, float& lo, float& hi) {
    asm("mov.b64 {%0, %1}, %2;" : "=f"(lo), "=f"(hi) : "l"(v));
}
__device__ __forceinline__ float ex2(float x) {
    float y;
    asm("ex2.approx.f32 %0, %1;" : "=f"(y) : "f"(x));
    return y;
}

// ---------------- mask build: warp per (n, word), coalesced graph reads -----
__global__ void build_mask_kernel(const int* __restrict__ graph) {
    int gwarp = (blockIdx.x * blockDim.x + threadIdx.x) >> 5;
    int lane  = threadIdx.x & 31;
    if (gwarp >= N_ * NW_) return;
    int n = gwarp >> 6;          // / NW_
    int w = gwarp & (NW_ - 1);
    int m = w * 32 + lane;
    bool bit = (graph[(size_t)n * N_ + m] != 0) || (m == n);
    unsigned word = __ballot_sync(0xffffffffu, bit);
    if (lane == 0) g_maskT[w * N_ + n] = word;
}

// ---------------- proj1: h[b,h,n,d] = sum_c x[b,n,c] * Wh[h,d,c] ------------
__global__ void proj1_kernel(const float* __restrict__ x,
                             const float* __restrict__ Wh) {
    __shared__ float xs[64][65];
    __shared__ float ws[64][65];
    int t    = threadIdx.x;              // 256 threads
    int row0 = blockIdx.x * 64;          // flattened b*N + n
    for (int i = t; i < 64 * 64; i += 256) {
        int r = i >> 6, c = i & 63;
        xs[r][c] = x[(size_t)(row0 + r) * C_ + c];
    }
    int d0 = (t & 15) * 4;
    int r0 = (t >> 4) * 4;
    int b     = row0 >> 11;              // / N_
    int nbase = row0 & (N_ - 1);
    for (int h = 0; h < H_; ++h) {
        __syncthreads();
        for (int i = t; i < 64 * 64; i += 256) {
            int r = i >> 6, c = i & 63;
            ws[r][c] = Wh[((size_t)h * D_ + r) * C_ + c];
        }
        __syncthreads();
        float acc[4][4] = {};
        #pragma unroll 8
        for (int c = 0; c < 64; ++c) {
            float xv[4], wv[4];
            #pragma unroll
            for (int i = 0; i < 4; ++i) { xv[i] = xs[r0 + i][c]; wv[i] = ws[d0 + i][c]; }
            #pragma unroll
            for (int i = 0; i < 4; ++i)
                #pragma unroll
                for (int j = 0; j < 4; ++j)
                    acc[i][j] += xv[i] * wv[j];
        }
        #pragma unroll
        for (int i = 0; i < 4; ++i)
            #pragma unroll
            for (int j = 0; j < 4; ++j)
                g_h[(((size_t)(b * H_ + h) * N_) + nbase + r0 + i) * D_ + d0 + j] = acc[i][j];
        __syncthreads();
    }
}

// ---------------- proj2: h2[b,n,d] = sum_k z[b,n,k] * Wo[d,k] ---------------
__global__ void proj2_kernel(const float* __restrict__ Wo) {
    __shared__ float zs[64][65];
    __shared__ float ws[64][65];
    int t    = threadIdx.x;
    int row0 = blockIdx.x * 64;
    int d0 = (t & 15) * 4;
    int r0 = (t >> 4) * 4;
    float acc[4][4] = {};
    for (int kc = 0; kc < 4; ++kc) {
        __syncthreads();
        for (int i = t; i < 64 * 64; i += 256) {
            int r = i >> 6, c = i & 63;
            zs[r][c] = g_z[(size_t)(row0 + r) * HD_ + kc * 64 + c];
            ws[r][c] = Wo[(size_t)r * HD_ + kc * 64 + c];
        }
        __syncthreads();
        #pragma unroll 8
        for (int c = 0; c < 64; ++c) {
            float xv[4], wv[4];
            #pragma unroll
            for (int i = 0; i < 4; ++i) { xv[i] = zs[r0 + i][c]; wv[i] = ws[d0 + i][c]; }
            #pragma unroll
            for (int i = 0; i < 4; ++i)
                #pragma unroll
                for (int j = 0; j < 4; ++j)
                    acc[i][j] += xv[i] * wv[j];
        }
    }
    #pragma unroll
    for (int i = 0; i < 4; ++i)
        #pragma unroll
        for (int j = 0; j < 4; ++j)
            g_h2[(size_t)(row0 + r0 + i) * D_ + d0 + j] = acc[i][j];
}

// ---------------- fused masked attention (1 thread = 1 query row) -----------
// Branch-free: every column computed; mask folds into a select on p.
// Softmax stabilized by subtracting the (always-unmasked) self-score ||q||^2.
// Diagonal term gives p = exp2(0) = 1 exactly, so sum >= 1 always.
// All dot products / accumulations use packed fma.rn.f32x2.
template <int LAYER>
__global__ void __launch_bounds__(128, 3)
attn_kernel(const float* __restrict__ bias,
            const float* __restrict__ gamma,
            const float* __restrict__ beta,
            float* __restrict__ outp) {
    __shared__ float4 ksm[64][16];       // 64 rows x 64 floats
    const int bh = blockIdx.x;
    const int n  = blockIdx.y * 128 + threadIdx.x;
    const float* hbase = (LAYER == 1 ? g_h : g_h2) + (size_t)bh * N_ * D_;

    // q row in packed registers (gmem bits reinterpreted as f32x2 pairs)
    ull qp[32];
    {
        const ulonglong2* qr = (const ulonglong2*)(hbase + (size_t)n * D_);
        #pragma unroll
        for (int k = 0; k < 16; ++k) {
            ulonglong2 v = qr[k];
            qp[2*k]   = v.x;
            qp[2*k+1] = v.y;
        }
    }
    // self-score * log2(e): the static softmax shift
    float qqL;
    {
        ull s2 = 0ull;
        #pragma unroll
        for (int k = 0; k < 32; ++k) s2 = fma2(qp[k], qp[k], s2);
        float lo, hi; upk2(s2, lo, hi);
        qqL = (lo + hi) * LOG2E;
    }

    ull ap[32];
    #pragma unroll
    for (int k = 0; k < 32; ++k) ap[k] = 0ull;
    float sum = 0.f;

    for (int tile = 0; tile < N_ / 64; ++tile) {
        __syncthreads();
        {
            const float4* src = (const float4*)(hbase + (size_t)tile * 64 * D_);
            float4* dst = (float4*)ksm;
            #pragma unroll
            for (int i = 0; i < 8; ++i) {
                int f = i * 128 + threadIdx.x;   // 0..1023 coalesced
                dst[f] = src[f];
            }
        }
        __syncthreads();
        unsigned w0 = g_maskT[(size_t)(tile * 2 + 0) * N_ + n];
        unsigned w1 = g_maskT[(size_t)(tile * 2 + 1) * N_ + n];
        #pragma unroll 1
        for (int half = 0; half < 2; ++half) {
            unsigned w = half ? w1 : w0;
            const ulonglong2* kbase = (const ulonglong2*)ksm[half * 32];
            #pragma unroll 1
            for (int j = 0; j < 32; ++j) {
                const ulonglong2* kp = kbase + j * 16;   // 64 floats = 16 ulonglong2 per row
                // scores: 32 FFMA2, two accumulators for ILP
                ull sa = 0ull, sb = 0ull;
                #pragma unroll
                for (int k = 0; k < 8; ++k) {
                    ulonglong2 kv0 = kp[2*k];
                    ulonglong2 kv1 = kp[2*k+1];
                    sa = fma2(qp[4*k+0], kv0.x, sa);
                    sb = fma2(qp[4*k+1], kv0.y, sb);
                    sa = fma2(qp[4*k+2], kv1.x, sa);
                    sb = fma2(qp[4*k+3], kv1.y, sb);
                }
                float l0, h0, l1, h1;
                upk2(sa, l0, h0); upk2(sb, l1, h1);
                float s = (l0 + h0) + (l1 + h1);
                float p = ex2(fmaf(s, LOG2E, -qqL));
                p = ((w >> j) & 1u) ? p : 0.f;       // branch-free mask
                sum += p;
                ull p2 = pk2(p, p);
                // accumulate: 32 FFMA2
                #pragma unroll
                for (int k = 0; k < 8; ++k) {
                    ulonglong2 kv0 = kp[2*k];
                    ulonglong2 kv1 = kp[2*k+1];
                    ap[4*k+0] = fma2(p2, kv0.x, ap[4*k+0]);
                    ap[4*k+1] = fma2(p2, kv0.y, ap[4*k+1]);
                    ap[4*k+2] = fma2(p2, kv1.x, ap[4*k+2]);
                    ap[4*k+3] = fma2(p2, kv1.y, ap[4*k+3]);
                }
            }
        }
    }

    // unpack accumulator
    float acc[64];
    #pragma unroll
    for (int k = 0; k < 32; ++k) upk2(ap[k], acc[2*k], acc[2*k+1]);

    float inv = 1.f / sum;   // diagonal contributes exactly 1 -> sum >= 1

    if (LAYER == 1) {
        int h = bh & (H_ - 1);
        int b = bh >> 2;
        const float* bp = bias + h * D_;
        float* zdst = g_z + ((size_t)b * N_ + n) * HD_ + h * D_;
        #pragma unroll
        for (int k4 = 0; k4 < 16; ++k4) {
            float4 v;
            float a0 = acc[4*k4+0] * inv + bp[4*k4+0];
            float a1 = acc[4*k4+1] * inv + bp[4*k4+1];
            float a2 = acc[4*k4+2] * inv + bp[4*k4+2];
            float a3 = acc[4*k4+3] * inv + bp[4*k4+3];
            v.x = a0 > 0.f ? a0 : 0.2f * a0;
            v.y = a1 > 0.f ? a1 : 0.2f * a1;
            v.z = a2 > 0.f ? a2 : 0.2f * a2;
            v.w = a3 > 0.f ? a3 : 0.2f * a3;
            ((float4*)zdst)[k4] = v;
        }
    } else {
        // +bo, leaky relu, LayerNorm over D=64 entirely in-thread
        float mu = 0.f;
        #pragma unroll
        for (int d = 0; d < 64; ++d) {
            float v = acc[d] * inv + bias[d];
            v = v > 0.f ? v : 0.2f * v;
            acc[d] = v;
            mu += v;
        }
        mu *= (1.f / 64.f);
        float var = 0.f;
        #pragma unroll
        for (int d = 0; d < 64; ++d) {
            float t = acc[d] - mu;
            var += t * t;
        }
        var *= (1.f / 64.f);
        float rs = rsqrtf(var + 1e-5f);
        float* od = outp + ((size_t)bh * N_ + n) * D_;
        #pragma unroll
        for (int k4 = 0; k4 < 16; ++k4) {
            float4 v;
            v.x = (acc[4*k4+0] - mu) * rs * gamma[4*k4+0] + beta[4*k4+0];
            v.y = (acc[4*k4+1] - mu) * rs * gamma[4*k4+1] + beta[4*k4+1];
            v.z = (acc[4*k4+2] - mu) * rs * gamma[4*k4+2] + beta[4*k4+2];
            v.w = (acc[4*k4+3] - mu) * rs * gamma[4*k4+3] + beta[4*k4+3];
            ((float4*)od)[k4] = v;
        }
    }
}

// ---------------- launch -----------------------------------------------------
extern "C" void kernel_launch(void* const* d_in, const int* in_sizes, int n_in,
                              void* d_out, int out_size) {
    const float* x     = (const float*)d_in[0];
    const int*   graph = (const int*)  d_in[1];
    const float* Wh    = (const float*)d_in[2];
    const float* bh    = (const float*)d_in[3];
    const float* Wo    = (const float*)d_in[4];
    const float* bo    = (const float*)d_in[5];
    const float* gamma = (const float*)d_in[6];
    const float* beta  = (const float*)d_in[7];
    float* out = (float*)d_out;

    build_mask_kernel<<<(N_ * NW_) / 8, 256>>>(graph);
    proj1_kernel<<<(B_ * N_) / 64, 256>>>(x, Wh);
    attn_kernel<1><<<dim3(B_ * H_, N_ / 128), 128>>>(bh, nullptr, nullptr, nullptr);
    proj2_kernel<<<(B_ * N_) / 64, 256>>>(Wo);
    attn_kernel<2><<<dim3(B_, N_ / 128), 128>>>(bo, gamma, beta, out);
}

// round 4
// speedup vs baseline: 1.4548x; 1.4548x over previous
#include <cuda_runtime.h>
#include <math_constants.h>

// Problem shape (fixed for this registry entry)
#define B_  8
#define N_  2048
#define C_  64
#define H_  4
#define D_  64
#define HD_ 256          // H*D
#define NW_ (N_/32)      // mask words per row = 64
#define LOG2E 1.4426950408889634f

// ---------------- scratch (device globals: no allocation allowed) -----------
__device__ float    g_h  [B_*H_*N_*D_];   // 16 MB  per-head projected features
__device__ float    g_z  [B_*N_*HD_];     // 16 MB  concat+lrelu of layer-1 output
__device__ float    g_h2 [B_*N_*D_];      //  4 MB  second projection
__device__ unsigned g_maskT[NW_*N_];      // 512 KB transposed bitmask [w][n]

__device__ __forceinline__ float ex2(float x) {
    float y;
    asm("ex2.approx.f32 %0, %1;" : "=f"(y) : "f"(x));
    return y;
}

// ---------------- mask build: warp per (n, word), coalesced graph reads -----
__global__ void build_mask_kernel(const int* __restrict__ graph) {
    int gwarp = (blockIdx.x * blockDim.x + threadIdx.x) >> 5;
    int lane  = threadIdx.x & 31;
    if (gwarp >= N_ * NW_) return;
    int n = gwarp >> 6;          // / NW_
    int w = gwarp & (NW_ - 1);
    int m = w * 32 + lane;
    bool bit = (graph[(size_t)n * N_ + m] != 0) || (m == n);
    unsigned word = __ballot_sync(0xffffffffu, bit);
    if (lane == 0) g_maskT[w * N_ + n] = word;
}

// ---------------- proj1: h[b,h,n,d] = sum_c x[b,n,c] * Wh[h,d,c] ------------
__global__ void proj1_kernel(const float* __restrict__ x,
                             const float* __restrict__ Wh) {
    __shared__ float xs[64][65];
    __shared__ float ws[64][65];
    int t    = threadIdx.x;              // 256 threads
    int row0 = blockIdx.x * 64;          // flattened b*N + n
    for (int i = t; i < 64 * 64; i += 256) {
        int r = i >> 6, c = i & 63;
        xs[r][c] = x[(size_t)(row0 + r) * C_ + c];
    }
    int d0 = (t & 15) * 4;
    int r0 = (t >> 4) * 4;
    int b     = row0 >> 11;              // / N_
    int nbase = row0 & (N_ - 1);
    for (int h = 0; h < H_; ++h) {
        __syncthreads();
        for (int i = t; i < 64 * 64; i += 256) {
            int r = i >> 6, c = i & 63;
            ws[r][c] = Wh[((size_t)h * D_ + r) * C_ + c];
        }
        __syncthreads();
        float acc[4][4] = {};
        #pragma unroll 8
        for (int c = 0; c < 64; ++c) {
            float xv[4], wv[4];
            #pragma unroll
            for (int i = 0; i < 4; ++i) { xv[i] = xs[r0 + i][c]; wv[i] = ws[d0 + i][c]; }
            #pragma unroll
            for (int i = 0; i < 4; ++i)
                #pragma unroll
                for (int j = 0; j < 4; ++j)
                    acc[i][j] += xv[i] * wv[j];
        }
        #pragma unroll
        for (int i = 0; i < 4; ++i)
            #pragma unroll
            for (int j = 0; j < 4; ++j)
                g_h[(((size_t)(b * H_ + h) * N_) + nbase + r0 + i) * D_ + d0 + j] = acc[i][j];
        __syncthreads();
    }
}

// ---------------- proj2: h2[b,n,d] = sum_k z[b,n,k] * Wo[d,k] ---------------
__global__ void proj2_kernel(const float* __restrict__ Wo) {
    __shared__ float zs[64][65];
    __shared__ float ws[64][65];
    int t    = threadIdx.x;
    int row0 = blockIdx.x * 64;
    int d0 = (t & 15) * 4;
    int r0 = (t >> 4) * 4;
    float acc[4][4] = {};
    for (int kc = 0; kc < 4; ++kc) {
        __syncthreads();
        for (int i = t; i < 64 * 64; i += 256) {
            int r = i >> 6, c = i & 63;
            zs[r][c] = g_z[(size_t)(row0 + r) * HD_ + kc * 64 + c];
            ws[r][c] = Wo[(size_t)r * HD_ + kc * 64 + c];
        }
        __syncthreads();
        #pragma unroll 8
        for (int c = 0; c < 64; ++c) {
            float xv[4], wv[4];
            #pragma unroll
            for (int i = 0; i < 4; ++i) { xv[i] = zs[r0 + i][c]; wv[i] = ws[d0 + i][c]; }
            #pragma unroll
            for (int i = 0; i < 4; ++i)
                #pragma unroll
                for (int j = 0; j < 4; ++j)
                    acc[i][j] += xv[i] * wv[j];
        }
    }
    #pragma unroll
    for (int i = 0; i < 4; ++i)
        #pragma unroll
        for (int j = 0; j < 4; ++j)
            g_h2[(size_t)(row0 + r0 + i) * D_ + d0 + j] = acc[i][j];
}

// ---------------- fused masked attention (1 thread = 1 query row) -----------
// Branch-free: every column computed; mask folds into a select on p.
// Softmax stabilized by subtracting the (always-unmasked) self-score ||q||^2:
// diagonal term contributes exp2(0) = 1 exactly, so sum >= 1 always.
// Plain scalar FFMA (ptxas-scheduled); no online max, no rescale, no branches.
template <int LAYER>
__global__ void __launch_bounds__(128, 3)
attn_kernel(const float* __restrict__ bias,
            const float* __restrict__ gamma,
            const float* __restrict__ beta,
            float* __restrict__ outp) {
    __shared__ float4 ksm[64][16];       // 64 rows x 64 floats
    const int bh = blockIdx.x;
    const int n  = blockIdx.y * 128 + threadIdx.x;
    const float* hbase = (LAYER == 1 ? g_h : g_h2) + (size_t)bh * N_ * D_;

    // q row in registers
    float q[64];
    {
        const float4* qr = (const float4*)(hbase + (size_t)n * D_);
        #pragma unroll
        for (int k4 = 0; k4 < 16; ++k4) {
            float4 v = qr[k4];
            q[4*k4+0] = v.x; q[4*k4+1] = v.y; q[4*k4+2] = v.z; q[4*k4+3] = v.w;
        }
    }
    // self-score * log2(e): the static softmax shift
    float qqL;
    {
        float t0 = 0.f, t1 = 0.f, t2 = 0.f, t3 = 0.f;
        #pragma unroll
        for (int k = 0; k < 16; ++k) {
            t0 += q[4*k+0] * q[4*k+0];
            t1 += q[4*k+1] * q[4*k+1];
            t2 += q[4*k+2] * q[4*k+2];
            t3 += q[4*k+3] * q[4*k+3];
        }
        qqL = ((t0 + t1) + (t2 + t3)) * LOG2E;
    }

    float acc[64];
    #pragma unroll
    for (int d = 0; d < 64; ++d) acc[d] = 0.f;
    float sum = 0.f;

    for (int tile = 0; tile < N_ / 64; ++tile) {
        __syncthreads();
        {
            const float4* src = (const float4*)(hbase + (size_t)tile * 64 * D_);
            float4* dst = (float4*)ksm;
            #pragma unroll
            for (int i = 0; i < 8; ++i) {
                int f = i * 128 + threadIdx.x;   // 0..1023 coalesced
                dst[f] = src[f];
            }
        }
        __syncthreads();
        unsigned w0 = g_maskT[(size_t)(tile * 2 + 0) * N_ + n];
        unsigned w1 = g_maskT[(size_t)(tile * 2 + 1) * N_ + n];
        #pragma unroll 1
        for (int half = 0; half < 2; ++half) {
            unsigned w = half ? w1 : w0;
            #pragma unroll 1
            for (int j = 0; j < 32; ++j) {
                const float4* kp = ksm[half * 32 + j];
                float s0 = 0.f, s1 = 0.f, s2 = 0.f, s3 = 0.f;
                #pragma unroll
                for (int k4 = 0; k4 < 16; ++k4) {
                    float4 kv = kp[k4];
                    s0 += q[4*k4+0] * kv.x;
                    s1 += q[4*k4+1] * kv.y;
                    s2 += q[4*k4+2] * kv.z;
                    s3 += q[4*k4+3] * kv.w;
                }
                float s = (s0 + s1) + (s2 + s3);
                float p = ex2(fmaf(s, LOG2E, -qqL));
                p = ((w >> j) & 1u) ? p : 0.f;       // branch-free mask
                sum += p;
                #pragma unroll
                for (int k4 = 0; k4 < 16; ++k4) {
                    float4 kv = kp[k4];
                    acc[4*k4+0] += p * kv.x;
                    acc[4*k4+1] += p * kv.y;
                    acc[4*k4+2] += p * kv.z;
                    acc[4*k4+3] += p * kv.w;
                }
            }
        }
    }

    float inv = 1.f / sum;   // diagonal contributes exactly 1 -> sum >= 1

    if (LAYER == 1) {
        int h = bh & (H_ - 1);
        int b = bh >> 2;
        const float* bp = bias + h * D_;
        float* zdst = g_z + ((size_t)b * N_ + n) * HD_ + h * D_;
        #pragma unroll
        for (int k4 = 0; k4 < 16; ++k4) {
            float4 v;
            float a0 = acc[4*k4+0] * inv + bp[4*k4+0];
            float a1 = acc[4*k4+1] * inv + bp[4*k4+1];
            float a2 = acc[4*k4+2] * inv + bp[4*k4+2];
            float a3 = acc[4*k4+3] * inv + bp[4*k4+3];
            v.x = a0 > 0.f ? a0 : 0.2f * a0;
            v.y = a1 > 0.f ? a1 : 0.2f * a1;
            v.z = a2 > 0.f ? a2 : 0.2f * a2;
            v.w = a3 > 0.f ? a3 : 0.2f * a3;
            ((float4*)zdst)[k4] = v;
        }
    } else {
        // +bo, leaky relu, LayerNorm over D=64 entirely in-thread
        float mu = 0.f;
        #pragma unroll
        for (int d = 0; d < 64; ++d) {
            float v = acc[d] * inv + bias[d];
            v = v > 0.f ? v : 0.2f * v;
            acc[d] = v;
            mu += v;
        }
        mu *= (1.f / 64.f);
        float var = 0.f;
        #pragma unroll
        for (int d = 0; d < 64; ++d) {
            float t = acc[d] - mu;
            var += t * t;
        }
        var *= (1.f / 64.f);
        float rs = rsqrtf(var + 1e-5f);
        float* od = outp + ((size_t)bh * N_ + n) * D_;
        #pragma unroll
        for (int k4 = 0; k4 < 16; ++k4) {
            float4 v;
            v.x = (acc[4*k4+0] - mu) * rs * gamma[4*k4+0] + beta[4*k4+0];
            v.y = (acc[4*k4+1] - mu) * rs * gamma[4*k4+1] + beta[4*k4+1];
            v.z = (acc[4*k4+2] - mu) * rs * gamma[4*k4+2] + beta[4*k4+2];
            v.w = (acc[4*k4+3] - mu) * rs * gamma[4*k4+3] + beta[4*k4+3];
            ((float4*)od)[k4] = v;
        }
    }
}

// ---------------- launch -----------------------------------------------------
extern "C" void kernel_launch(void* const* d_in, const int* in_sizes, int n_in,
                              void* d_out, int out_size) {
    const float* x     = (const float*)d_in[0];
    const int*   graph = (const int*)  d_in[1];
    const float* Wh    = (const float*)d_in[2];
    const float* bh    = (const float*)d_in[3];
    const float* Wo    = (const float*)d_in[4];
    const float* bo    = (const float*)d_in[5];
    const float* gamma = (const float*)d_in[6];
    const float* beta  = (const float*)d_in[7];
    float* out = (float*)d_out;

    build_mask_kernel<<<(N_ * NW_) / 8, 256>>>(graph);
    proj1_kernel<<<(B_ * N_) / 64, 256>>>(x, Wh);
    attn_kernel<1><<<dim3(B_ * H_, N_ / 128), 128>>>(bh, nullptr, nullptr, nullptr);
    proj2_kernel<<<(B_ * N_) / 64, 256>>>(Wo);
    attn_kernel<2><<<dim3(B_, N_ / 128), 128>>>(bo, gamma, beta, out);
}

// round 5
// speedup vs baseline: 3.9240x; 2.6973x over previous
#include <cuda_runtime.h>
#include <math_constants.h>

// Problem shape (fixed for this registry entry)
#define B_  8
#define N_  2048
#define C_  64
#define H_  4
#define D_  64
#define HD_ 256          // H*D
#define NW_ (N_/32)      // mask words per row = 64
#define LOG2E 1.4426950408889634f

#define BM 128           // queries per block
#define BN 64            // K columns per tile
#define QT_S 132         // Qt row stride (floats)
#define K_S  68          // Kd/Kc row stride
#define PT_S 132         // Pt row stride

// dynamic smem layout (float offsets)
#define OFF_QT 0                       // Qt[64][132]            8448
#define OFF_KD (OFF_QT + 64*QT_S)      // Kd[64][68]  (K^T: [d][c]) 4352
#define OFF_KC (OFF_KD + 64*K_S)       // Kc[64][68]  ([c][d])      4352
#define OFF_PT (OFF_KC + 64*K_S)       // Pt[64][132] ([c][r])      8448
#define OFF_MW (OFF_PT + 64*PT_S)      // mask words 2*128 (as uint) 256
#define OFF_QQ (OFF_MW + 256)          // qq[128]
#define OFF_RS (OFF_QQ + 128)          // rowsum[128]
#define SMEM_FLOATS (OFF_RS + 128)
#define SMEM_BYTES (SMEM_FLOATS * 4)   // 104448 B

// ---------------- scratch (device globals: no allocation allowed) -----------
__device__ float    g_h  [B_*H_*N_*D_];   // 16 MB  per-head projected features
__device__ float    g_z  [B_*N_*HD_];     // 16 MB  concat+lrelu of layer-1 output
__device__ float    g_h2 [B_*N_*D_];      //  4 MB  second projection
__device__ unsigned g_maskT[NW_*N_];      // 512 KB transposed bitmask [w][n]

__device__ __forceinline__ float ex2(float x) {
    float y;
    asm("ex2.approx.f32 %0, %1;" : "=f"(y) : "f"(x));
    return y;
}

// ---------------- mask build: warp per (n, word), coalesced graph reads -----
__global__ void build_mask_kernel(const int* __restrict__ graph) {
    int gwarp = (blockIdx.x * blockDim.x + threadIdx.x) >> 5;
    int lane  = threadIdx.x & 31;
    if (gwarp >= N_ * NW_) return;
    int n = gwarp >> 6;          // / NW_
    int w = gwarp & (NW_ - 1);
    int m = w * 32 + lane;
    bool bit = (graph[(size_t)n * N_ + m] != 0) || (m == n);
    unsigned word = __ballot_sync(0xffffffffu, bit);
    if (lane == 0) g_maskT[w * N_ + n] = word;
}

// ---------------- proj1: h[b,h,n,d] = sum_c x[b,n,c] * Wh[h,d,c] ------------
__global__ void proj1_kernel(const float* __restrict__ x,
                             const float* __restrict__ Wh) {
    __shared__ float xs[64][65];
    __shared__ float ws[64][65];
    int t    = threadIdx.x;              // 256 threads
    int row0 = blockIdx.x * 64;          // flattened b*N + n
    for (int i = t; i < 64 * 64; i += 256) {
        int r = i >> 6, c = i & 63;
        xs[r][c] = x[(size_t)(row0 + r) * C_ + c];
    }
    int d0 = (t & 15) * 4;
    int r0 = (t >> 4) * 4;
    int b     = row0 >> 11;              // / N_
    int nbase = row0 & (N_ - 1);
    for (int h = 0; h < H_; ++h) {
        __syncthreads();
        for (int i = t; i < 64 * 64; i += 256) {
            int r = i >> 6, c = i & 63;
            ws[r][c] = Wh[((size_t)h * D_ + r) * C_ + c];
        }
        __syncthreads();
        float acc[4][4] = {};
        #pragma unroll 8
        for (int c = 0; c < 64; ++c) {
            float xv[4], wv[4];
            #pragma unroll
            for (int i = 0; i < 4; ++i) { xv[i] = xs[r0 + i][c]; wv[i] = ws[d0 + i][c]; }
            #pragma unroll
            for (int i = 0; i < 4; ++i)
                #pragma unroll
                for (int j = 0; j < 4; ++j)
                    acc[i][j] += xv[i] * wv[j];
        }
        #pragma unroll
        for (int i = 0; i < 4; ++i)
            #pragma unroll
            for (int j = 0; j < 4; ++j)
                g_h[(((size_t)(b * H_ + h) * N_) + nbase + r0 + i) * D_ + d0 + j] = acc[i][j];
        __syncthreads();
    }
}

// ---------------- proj2: h2[b,n,d] = sum_k z[b,n,k] * Wo[d,k] ---------------
__global__ void proj2_kernel(const float* __restrict__ Wo) {
    __shared__ float zs[64][65];
    __shared__ float ws[64][65];
    int t    = threadIdx.x;
    int row0 = blockIdx.x * 64;
    int d0 = (t & 15) * 4;
    int r0 = (t >> 4) * 4;
    float acc[4][4] = {};
    for (int kc = 0; kc < 4; ++kc) {
        __syncthreads();
        for (int i = t; i < 64 * 64; i += 256) {
            int r = i >> 6, c = i & 63;
            zs[r][c] = g_z[(size_t)(row0 + r) * HD_ + kc * 64 + c];
            ws[r][c] = Wo[(size_t)r * HD_ + kc * 64 + c];
        }
        __syncthreads();
        #pragma unroll 8
        for (int c = 0; c < 64; ++c) {
            float xv[4], wv[4];
            #pragma unroll
            for (int i = 0; i < 4; ++i) { xv[i] = zs[r0 + i][c]; wv[i] = ws[d0 + i][c]; }
            #pragma unroll
            for (int i = 0; i < 4; ++i)
                #pragma unroll
                for (int j = 0; j < 4; ++j)
                    acc[i][j] += xv[i] * wv[j];
        }
    }
    #pragma unroll
    for (int i = 0; i < 4; ++i)
        #pragma unroll
        for (int j = 0; j < 4; ++j)
            g_h2[(size_t)(row0 + r0 + i) * D_ + d0 + j] = acc[i][j];
}

// ---------------- tiled masked attention (register-tiled GEMM pair) ---------
// Block: 128 queries of one (b,h). Per 64-col tile:
//   GEMM-S: S = Q K^T  (thread tile 8 rows x 4 cols; Qt/Kd transposed in smem)
//   exp/mask in regs -> Pt (transposed) ; row-sum partials in regs
//   GEMM-A: acc += P K (thread tile 8 rows x 4 dims; Pt/Kc in smem)
// Softmax shift = ||q||^2 (diagonal always unmasked -> sum >= ~1).
template <int LAYER>
__global__ void __launch_bounds__(256, 2)
attn_tiled(const float* __restrict__ bias,
           const float* __restrict__ gamma,
           const float* __restrict__ beta,
           float* __restrict__ outp) {
    extern __shared__ float sm[];
    float*    Qt = sm + OFF_QT;
    float*    Kd = sm + OFF_KD;
    float*    Kc = sm + OFF_KC;
    float*    Pt = sm + OFF_PT;
    unsigned* mw = (unsigned*)(sm + OFF_MW);
    float*    qq = sm + OFF_QQ;
    float*    rowsum = sm + OFF_RS;

    const int bh   = blockIdx.x;
    const int row0 = blockIdx.y * BM;
    const float* hbase = (LAYER == 1 ? g_h : g_h2) + (size_t)bh * N_ * D_;

    const int t  = threadIdx.x;
    const int tr = t >> 4;           // 0..15
    const int tc = t & 15;           // 0..15
    const int r0 = tr * 8;           // rows in block tile
    const int c0 = tc * 4;           // cols (GEMM-S) / dims (GEMM-A)

    // ---- stage Q transposed: Qt[d][r] ----
    #pragma unroll
    for (int i = 0; i < 32; ++i) {
        int lin = t + i * 256;
        int r = lin >> 6, d = lin & 63;
        Qt[d * QT_S + r] = hbase[(size_t)(row0 + r) * D_ + d];
    }
    __syncthreads();
    if (t < 128) {
        float s = 0.f;
        #pragma unroll 16
        for (int d = 0; d < 64; ++d) { float v = Qt[d * QT_S + t]; s += v * v; }
        qq[t] = s * LOG2E;
    }

    float acc[8][4];
    #pragma unroll
    for (int i = 0; i < 8; ++i)
        #pragma unroll
        for (int j = 0; j < 4; ++j) acc[i][j] = 0.f;
    float rs[8];
    #pragma unroll
    for (int i = 0; i < 8; ++i) rs[i] = 0.f;

    for (int tile = 0; tile < N_ / BN; ++tile) {
        __syncthreads();   // previous tile's GEMM-A done (and qq visible on iter 0)
        // ---- stage K tile: Kc[c][d] (float4) and Kd[d][c] (transpose) ----
        {
            const float4* src = (const float4*)(hbase + (size_t)tile * BN * D_);
            #pragma unroll
            for (int i = 0; i < 4; ++i) {
                int lin4 = t + i * 256;          // 0..1023
                int c = lin4 >> 4, d4 = (lin4 & 15) * 4;
                float4 v = src[lin4];
                *(float4*)&Kc[c * K_S + d4] = v;
                Kd[(d4 + 0) * K_S + c] = v.x;
                Kd[(d4 + 1) * K_S + c] = v.y;
                Kd[(d4 + 2) * K_S + c] = v.z;
                Kd[(d4 + 3) * K_S + c] = v.w;
            }
            int w = t >> 7, n = t & 127;
            mw[w * 128 + n] = g_maskT[(size_t)(tile * 2 + w) * N_ + row0 + n];
        }
        __syncthreads();

        // ---- GEMM-S: sv[i][j] = sum_d Qt[d][r0+i] * Kd[d][c0+j] ----
        float sv[8][4];
        #pragma unroll
        for (int i = 0; i < 8; ++i)
            #pragma unroll
            for (int j = 0; j < 4; ++j) sv[i][j] = 0.f;
        #pragma unroll 8
        for (int d = 0; d < 64; ++d) {
            float4 qa = *(const float4*)&Qt[d * QT_S + r0];
            float4 qb = *(const float4*)&Qt[d * QT_S + r0 + 4];
            float4 kv = *(const float4*)&Kd[d * K_S + c0];
            float qv[8] = {qa.x, qa.y, qa.z, qa.w, qb.x, qb.y, qb.z, qb.w};
            float kw[4] = {kv.x, kv.y, kv.z, kv.w};
            #pragma unroll
            for (int i = 0; i < 8; ++i)
                #pragma unroll
                for (int j = 0; j < 4; ++j)
                    sv[i][j] += qv[i] * kw[j];
        }

        // ---- mask + exp -> Pt, rowsum partials ----
        const int wsel = (tc >> 3) * 128;
        const int bsh  = c0 & 31;
        #pragma unroll
        for (int i = 0; i < 8; ++i) {
            unsigned word = mw[wsel + r0 + i];
            float qqr = qq[r0 + i];
            #pragma unroll
            for (int j = 0; j < 4; ++j) {
                float p = ex2(fmaf(sv[i][j], LOG2E, -qqr));
                p = ((word >> (bsh + j)) & 1u) ? p : 0.f;
                Pt[(c0 + j) * PT_S + r0 + i] = p;
                rs[i] += p;
            }
        }
        __syncthreads();

        // ---- GEMM-A: acc[i][j] += sum_c Pt[c][r0+i] * Kc[c][c0+j] ----
        #pragma unroll 8
        for (int c = 0; c < 64; ++c) {
            float4 pa = *(const float4*)&Pt[c * PT_S + r0];
            float4 pb = *(const float4*)&Pt[c * PT_S + r0 + 4];
            float4 kv = *(const float4*)&Kc[c * K_S + c0];
            float pv[8] = {pa.x, pa.y, pa.z, pa.w, pb.x, pb.y, pb.z, pb.w};
            float kw[4] = {kv.x, kv.y, kv.z, kv.w};
            #pragma unroll
            for (int i = 0; i < 8; ++i)
                #pragma unroll
                for (int j = 0; j < 4; ++j)
                    acc[i][j] += pv[i] * kw[j];
        }
    }

    // ---- row-sum reduce: threads sharing rows are lanes 0-15 / 16-31 ----
    #pragma unroll
    for (int i = 0; i < 8; ++i) {
        #pragma unroll
        for (int m = 8; m >= 1; m >>= 1)
            rs[i] += __shfl_xor_sync(0xffffffffu, rs[i], m);
    }
    if (tc == 0) {
        #pragma unroll
        for (int i = 0; i < 8; ++i) rowsum[r0 + i] = rs[i];
    }
    __syncthreads();

    if (LAYER == 1) {
        int h = bh & (H_ - 1);
        int b = bh >> 2;
        #pragma unroll
        for (int i = 0; i < 8; ++i) {
            float inv = 1.f / rowsum[r0 + i];
            float4 v;
            float a0 = acc[i][0] * inv + bias[h * D_ + c0 + 0];
            float a1 = acc[i][1] * inv + bias[h * D_ + c0 + 1];
            float a2 = acc[i][2] * inv + bias[h * D_ + c0 + 2];
            float a3 = acc[i][3] * inv + bias[h * D_ + c0 + 3];
            v.x = a0 > 0.f ? a0 : 0.2f * a0;
            v.y = a1 > 0.f ? a1 : 0.2f * a1;
            v.z = a2 > 0.f ? a2 : 0.2f * a2;
            v.w = a3 > 0.f ? a3 : 0.2f * a3;
            *(float4*)&g_z[((size_t)(b * N_ + row0 + r0 + i)) * HD_ + h * D_ + c0] = v;
        }
    } else {
        // write lrelu(acc/sum + bo) into smem buf[128][68] (reuses Qt/Kd region),
        // then LayerNorm per row
        float* buf = sm;     // stride 68, 128*68 = 8704 floats < OFF_KC
        #pragma unroll
        for (int i = 0; i < 8; ++i) {
            float inv = 1.f / rowsum[r0 + i];
            #pragma unroll
            for (int j = 0; j < 4; ++j) {
                float a = acc[i][j] * inv + bias[c0 + j];
                a = a > 0.f ? a : 0.2f * a;
                buf[(r0 + i) * 68 + c0 + j] = a;
            }
        }
        __syncthreads();
        if (t < 128) {
            const float* br = buf + t * 68;
            float mu = 0.f;
            #pragma unroll 16
            for (int d = 0; d < 64; ++d) mu += br[d];
            mu *= (1.f / 64.f);
            float var = 0.f;
            #pragma unroll 16
            for (int d = 0; d < 64; ++d) { float u = br[d] - mu; var += u * u; }
            var *= (1.f / 64.f);
            float rstd = rsqrtf(var + 1e-5f);
            float* od = outp + ((size_t)bh * N_ + row0 + t) * D_;
            #pragma unroll 16
            for (int d = 0; d < 64; ++d)
                od[d] = (br[d] - mu) * rstd * gamma[d] + beta[d];
        }
    }
}

// ---------------- launch -----------------------------------------------------
extern "C" void kernel_launch(void* const* d_in, const int* in_sizes, int n_in,
                              void* d_out, int out_size) {
    const float* x     = (const float*)d_in[0];
    const int*   graph = (const int*)  d_in[1];
    const float* Wh    = (const float*)d_in[2];
    const float* bh    = (const float*)d_in[3];
    const float* Wo    = (const float*)d_in[4];
    const float* bo    = (const float*)d_in[5];
    const float* gamma = (const float*)d_in[6];
    const float* beta  = (const float*)d_in[7];
    float* out = (float*)d_out;

    // host-side attribute set (not a stream op; safe under graph capture)
    cudaFuncSetAttribute(attn_tiled<1>, cudaFuncAttributeMaxDynamicSharedMemorySize, SMEM_BYTES);
    cudaFuncSetAttribute(attn_tiled<2>, cudaFuncAttributeMaxDynamicSharedMemorySize, SMEM_BYTES);

    build_mask_kernel<<<(N_ * NW_) / 8, 256>>>(graph);
    proj1_kernel<<<(B_ * N_) / 64, 256>>>(x, Wh);
    attn_tiled<1><<<dim3(B_ * H_, N_ / BM), 256, SMEM_BYTES>>>(bh, nullptr, nullptr, nullptr);
    proj2_kernel<<<(B_ * N_) / 64, 256>>>(Wo);
    attn_tiled<2><<<dim3(B_, N_ / BM), 256, SMEM_BYTES>>>(bo, gamma, beta, out);
}

// round 7
// speedup vs baseline: 10.4749x; 2.6694x over previous
#include <cuda_runtime.h>
#include <cuda_fp16.h>
#include <cstdint>

// Problem shape (fixed for this registry entry)
#define B_  8
#define N_  2048
#define C_  64
#define H_  4
#define D_  64
#define HD_ 256          // H*D
#define NW_ (N_/32)      // mask words per row = 64
#define LOG2E 1.4426950408889634f

// ---------------- scratch (device globals: no allocation allowed) -----------
__device__ __half  g_hH [B_*H_*N_*D_];    // 8 MB  layer1 features, f16 hi
__device__ __half  g_hL [B_*H_*N_*D_];    // 8 MB  layer1 features, f16 lo (residual)
__device__ __half  g_h2H[B_*N_*D_];       // 2 MB  layer2 features hi
__device__ __half  g_h2L[B_*N_*D_];       // 2 MB  layer2 features lo
__device__ float    g_z  [B_*N_*HD_];     // 16 MB concat+lrelu of layer-1 output
__device__ unsigned g_maskT[NW_*N_];      // transposed bitmask [w][n]

__device__ __forceinline__ float ex2(float x) {
    float y;
    asm("ex2.approx.f32 %0, %1;" : "=f"(y) : "f"(x));
    return y;
}
__device__ __forceinline__ uint32_t smem_u32(const void* p) {
    uint32_t a;
    asm("{ .reg .u64 t; cvta.to.shared.u64 t, %1; cvt.u32.u64 %0, t; }" : "=r"(a) : "l"(p));
    return a;
}
__device__ __forceinline__ void ldsm4(uint32_t r[4], uint32_t addr) {
    asm volatile("ldmatrix.sync.aligned.m8n8.x4.shared.b16 {%0,%1,%2,%3}, [%4];"
                 : "=r"(r[0]), "=r"(r[1]), "=r"(r[2]), "=r"(r[3]) : "r"(addr));
}
__device__ __forceinline__ void ldsm4t(uint32_t r[4], uint32_t addr) {
    asm volatile("ldmatrix.sync.aligned.m8n8.x4.trans.shared.b16 {%0,%1,%2,%3}, [%4];"
                 : "=r"(r[0]), "=r"(r[1]), "=r"(r[2]), "=r"(r[3]) : "r"(addr));
}
__device__ __forceinline__ void mma16816(float d[4], const uint32_t a[4], const uint32_t b[2]) {
    asm volatile("mma.sync.aligned.m16n8k16.row.col.f32.f16.f16.f32 "
                 "{%0,%1,%2,%3}, {%4,%5,%6,%7}, {%8,%9}, {%0,%1,%2,%3};"
                 : "+f"(d[0]), "+f"(d[1]), "+f"(d[2]), "+f"(d[3])
                 : "r"(a[0]), "r"(a[1]), "r"(a[2]), "r"(a[3]), "r"(b[0]), "r"(b[1]));
}
__device__ __forceinline__ float lrelu(float a) { return a > 0.f ? a : 0.2f * a; }

// split a float into f16 hi + f16 lo(residual), store via half2
__device__ __forceinline__ void split_store(__half* dH, __half* dL, size_t idx,
                                            float v0, float v1) {
    __half h0 = __float2half_rn(v0), h1 = __float2half_rn(v1);
    __half l0 = __float2half_rn(v0 - __half2float(h0));
    __half l1 = __float2half_rn(v1 - __half2float(h1));
    *(__half2*)&dH[idx] = __halves2half2(h0, h1);
    *(__half2*)&dL[idx] = __halves2half2(l0, l1);
}

// ---------------- mask build ------------------------------------------------
__global__ void build_mask_kernel(const int* __restrict__ graph) {
    int gwarp = (blockIdx.x * blockDim.x + threadIdx.x) >> 5;
    int lane  = threadIdx.x & 31;
    if (gwarp >= N_ * NW_) return;
    int n = gwarp >> 6;
    int w = gwarp & (NW_ - 1);
    int m = w * 32 + lane;
    bool bit = (graph[(size_t)n * N_ + m] != 0) || (m == n);
    unsigned word = __ballot_sync(0xffffffffu, bit);
    if (lane == 0) g_maskT[w * N_ + n] = word;
}

// ---------------- proj1: h[b,h,n,d] = sum_c x[b,n,c]*Wh[h,d,c] -> f16 hi/lo -
__global__ void proj1_kernel(const float* __restrict__ x,
                             const float* __restrict__ Wh) {
    __shared__ float xs[64][65];
    __shared__ float ws[64][65];
    int t    = threadIdx.x;
    int row0 = blockIdx.x * 64;
    for (int i = t; i < 64 * 64; i += 256) {
        int r = i >> 6, c = i & 63;
        xs[r][c] = x[(size_t)(row0 + r) * C_ + c];
    }
    int d0 = (t & 15) * 4;
    int r0 = (t >> 4) * 4;
    int b     = row0 >> 11;
    int nbase = row0 & (N_ - 1);
    for (int h = 0; h < H_; ++h) {
        __syncthreads();
        for (int i = t; i < 64 * 64; i += 256) {
            int r = i >> 6, c = i & 63;
            ws[r][c] = Wh[((size_t)h * D_ + r) * C_ + c];
        }
        __syncthreads();
        float acc[4][4] = {};
        #pragma unroll 8
        for (int c = 0; c < 64; ++c) {
            float xv[4], wv[4];
            #pragma unroll
            for (int i = 0; i < 4; ++i) { xv[i] = xs[r0 + i][c]; wv[i] = ws[d0 + i][c]; }
            #pragma unroll
            for (int i = 0; i < 4; ++i)
                #pragma unroll
                for (int j = 0; j < 4; ++j)
                    acc[i][j] += xv[i] * wv[j];
        }
        #pragma unroll
        for (int i = 0; i < 4; ++i) {
            size_t base = (((size_t)(b * H_ + h) * N_) + nbase + r0 + i) * D_ + d0;
            split_store(g_hH, g_hL, base,     acc[i][0], acc[i][1]);
            split_store(g_hH, g_hL, base + 2, acc[i][2], acc[i][3]);
        }
        __syncthreads();
    }
}

// ---------------- proj2: h2[b,n,d] = sum_k z[b,n,k]*Wo[d,k] -> f16 hi/lo ----
__global__ void proj2_kernel(const float* __restrict__ Wo) {
    __shared__ float zs[64][65];
    __shared__ float ws[64][65];
    int t    = threadIdx.x;
    int row0 = blockIdx.x * 64;
    int d0 = (t & 15) * 4;
    int r0 = (t >> 4) * 4;
    float acc[4][4] = {};
    for (int kc = 0; kc < 4; ++kc) {
        __syncthreads();
        for (int i = t; i < 64 * 64; i += 256) {
            int r = i >> 6, c = i & 63;
            zs[r][c] = g_z[(size_t)(row0 + r) * HD_ + kc * 64 + c];
            ws[r][c] = Wo[(size_t)r * HD_ + kc * 64 + c];
        }
        __syncthreads();
        #pragma unroll 8
        for (int c = 0; c < 64; ++c) {
            float xv[4], wv[4];
            #pragma unroll
            for (int i = 0; i < 4; ++i) { xv[i] = zs[r0 + i][c]; wv[i] = ws[d0 + i][c]; }
            #pragma unroll
            for (int i = 0; i < 4; ++i)
                #pragma unroll
                for (int j = 0; j < 4; ++j)
                    acc[i][j] += xv[i] * wv[j];
        }
    }
    #pragma unroll
    for (int i = 0; i < 4; ++i) {
        size_t base = (size_t)(row0 + r0 + i) * D_ + d0;
        split_store(g_h2H, g_h2L, base,     acc[i][0], acc[i][1]);
        split_store(g_h2H, g_h2L, base + 2, acc[i][2], acc[i][3]);
    }
}

// ================= HMMA (mma.sync) flash attention ==========================
// 256 threads = 8 warps; warp w owns query rows 16w..16w+15 of a 128-row block.
// KV tile = 128. S = QhKh + QhKl + QlKh (f16 3-term), P f16, O = P(Vh + Vl).
#define SQ 72                         // smem row stride in halves (144B: conflict-free)
#define SM_QH 0
#define SM_QL 9216
#define SM_KH 18432
#define SM_KL 27648
#define SMEM_ATT (36864 * 2)          // 73728 bytes

template <int LAYER>
__global__ void __launch_bounds__(256, 1)
attn_mma(const float* __restrict__ bias,
         const float* __restrict__ gamma,
         const float* __restrict__ beta,
         float* __restrict__ outp) {
    extern __shared__ __half smh[];
    const int t    = threadIdx.x;
    const int wid  = t >> 5;
    const int lane = t & 31;
    const int g    = lane >> 2;
    const int tg   = lane & 3;
    const int wr0  = wid << 4;
    const int bh   = blockIdx.x;
    const int row0 = blockIdx.y << 7;
    const __half* hH = (LAYER == 1 ? g_hH : g_h2H) + (size_t)bh * (N_ * D_);
    const __half* hL = (LAYER == 1 ? g_hL : g_h2L) + (size_t)bh * (N_ * D_);
    const uint32_t sbase = smem_u32(smh);

    // ---- stage Q (block's 128 rows), hi+lo ----
    {
        const uint4* sH = (const uint4*)(hH + (size_t)row0 * D_);
        const uint4* sL = (const uint4*)(hL + (size_t)row0 * D_);
        #pragma unroll
        for (int i = 0; i < 4; ++i) {
            int idx = t + (i << 8);            // 0..1023; 8 uint4 per row
            int r = idx >> 3, c8 = (idx & 7) << 3;
            *(uint4*)&smh[SM_QH + r * SQ + c8] = sH[idx];
            *(uint4*)&smh[SM_QL + r * SQ + c8] = sL[idx];
        }
    }
    __syncthreads();

    // ---- preload Q A-frags (row-major m16k16): 4 kf x {hi,lo} ----
    uint32_t qh[4][4], ql[4][4];
    {
        int arow  = wr0 + (lane & 15);
        int acolb = (lane >> 4) << 3;
        #pragma unroll
        for (int kf = 0; kf < 4; ++kf) {
            ldsm4(qh[kf], sbase + ((uint32_t)(SM_QH + arow * SQ + (kf << 4) + acolb) << 1));
            ldsm4(ql[kf], sbase + ((uint32_t)(SM_QL + arow * SQ + (kf << 4) + acolb) << 1));
        }
    }

    float oacc[8][4];
    #pragma unroll
    for (int i = 0; i < 8; ++i)
        #pragma unroll
        for (int j = 0; j < 4; ++j) oacc[i][j] = 0.f;
    float rs0 = 0.f, rs1 = 0.f, mr0 = -1e30f, mr1 = -1e30f;
    const int grow0 = row0 + wr0 + g;

    #pragma unroll 1
    for (int tile = 0; tile < N_ / 128; ++tile) {
        __syncthreads();
        // ---- stage K tile (128 rows), hi+lo ----
        {
            const uint4* sH = (const uint4*)(hH + (size_t)tile * (128 * D_));
            const uint4* sL = (const uint4*)(hL + (size_t)tile * (128 * D_));
            #pragma unroll
            for (int i = 0; i < 4; ++i) {
                int idx = t + (i << 8);
                int r = idx >> 3, c8 = (idx & 7) << 3;
                *(uint4*)&smh[SM_KH + r * SQ + c8] = sH[idx];
                *(uint4*)&smh[SM_KL + r * SQ + c8] = sL[idx];
            }
        }
        unsigned mw0[4], mw1[4];
        #pragma unroll
        for (int w = 0; w < 4; ++w) {
            mw0[w] = g_maskT[(size_t)((tile << 2) + w) * N_ + grow0];
            mw1[w] = g_maskT[(size_t)((tile << 2) + w) * N_ + grow0 + 8];
        }
        __syncthreads();

        // ---- GEMM-S: sacc[16 nfrags][4] over 4 kf, 3 split terms ----
        float sacc[16][4];
        #pragma unroll
        for (int i = 0; i < 16; ++i)
            #pragma unroll
            for (int j = 0; j < 4; ++j) sacc[i][j] = 0.f;
        {
            const int brow = ((lane >> 4) << 3) + (lane & 7);
            const int bcol = ((lane >> 3) & 1) << 3;
            #pragma unroll
            for (int kf = 0; kf < 4; ++kf) {
                #pragma unroll
                for (int hseg = 0; hseg < 2; ++hseg) {      // nf 0..7, then 8..15
                    uint32_t bfr[8][2];
                    #pragma unroll
                    for (int j = 0; j < 4; ++j) {
                        uint32_t r4[4];
                        int jj = hseg * 4 + j;
                        ldsm4(r4, sbase + ((uint32_t)(SM_KH + ((jj << 4) + brow) * SQ
                                                      + (kf << 4) + bcol) << 1));
                        bfr[2*j][0] = r4[0]; bfr[2*j][1] = r4[1];
                        bfr[2*j+1][0] = r4[2]; bfr[2*j+1][1] = r4[3];
                    }
                    #pragma unroll
                    for (int nf = 0; nf < 8; ++nf) mma16816(sacc[hseg*8+nf], qh[kf], bfr[nf]);
                    #pragma unroll
                    for (int nf = 0; nf < 8; ++nf) mma16816(sacc[hseg*8+nf], ql[kf], bfr[nf]);
                    #pragma unroll
                    for (int j = 0; j < 4; ++j) {
                        uint32_t r4[4];
                        int jj = hseg * 4 + j;
                        ldsm4(r4, sbase + ((uint32_t)(SM_KL + ((jj << 4) + brow) * SQ
                                                      + (kf << 4) + bcol) << 1));
                        bfr[2*j][0] = r4[0]; bfr[2*j][1] = r4[1];
                        bfr[2*j+1][0] = r4[2]; bfr[2*j+1][1] = r4[3];
                    }
                    #pragma unroll
                    for (int nf = 0; nf < 8; ++nf) mma16816(sacc[hseg*8+nf], qh[kf], bfr[nf]);
                }
            }
        }

        // ---- masked online softmax; P -> A-frags in registers ----
        float m0 = -1e30f, m1 = -1e30f;
        #pragma unroll
        for (int nf = 0; nf < 16; ++nf) {
            unsigned w0 = mw0[nf >> 2], w1 = mw1[nf >> 2];
            int bb = ((nf & 3) << 3) + (tg << 1);
            m0 = fmaxf(m0, ((w0 >> bb) & 1u)       ? sacc[nf][0] : -1e30f);
            m0 = fmaxf(m0, ((w0 >> (bb + 1)) & 1u) ? sacc[nf][1] : -1e30f);
            m1 = fmaxf(m1, ((w1 >> bb) & 1u)       ? sacc[nf][2] : -1e30f);
            m1 = fmaxf(m1, ((w1 >> (bb + 1)) & 1u) ? sacc[nf][3] : -1e30f);
        }
        m0 = fmaxf(m0, __shfl_xor_sync(0xffffffffu, m0, 1));
        m0 = fmaxf(m0, __shfl_xor_sync(0xffffffffu, m0, 2));
        m1 = fmaxf(m1, __shfl_xor_sync(0xffffffffu, m1, 1));
        m1 = fmaxf(m1, __shfl_xor_sync(0xffffffffu, m1, 2));
        float mn0 = fmaxf(mr0, m0), mn1 = fmaxf(mr1, m1);
        float al0 = ex2((mr0 - mn0) * LOG2E), al1 = ex2((mr1 - mn1) * LOG2E);
        mr0 = mn0; mr1 = mn1;
        rs0 *= al0; rs1 *= al1;
        #pragma unroll
        for (int nf = 0; nf < 8; ++nf) {
            oacc[nf][0] *= al0; oacc[nf][1] *= al0;
            oacc[nf][2] *= al1; oacc[nf][3] *= al1;
        }
        const float mL0 = mn0 * LOG2E, mL1 = mn1 * LOG2E;
        uint32_t pa[8][4];
        #pragma unroll
        for (int k2 = 0; k2 < 8; ++k2) {
            int nfA = k2 << 1, nfB = nfA + 1;
            unsigned wA0 = mw0[nfA >> 2], wA1 = mw1[nfA >> 2];
            unsigned wB0 = mw0[nfB >> 2], wB1 = mw1[nfB >> 2];
            int bbA = ((nfA & 3) << 3) + (tg << 1);
            int bbB = ((nfB & 3) << 3) + (tg << 1);
            float p00 = ((wA0 >> bbA) & 1u)     ? ex2(fmaf(sacc[nfA][0], LOG2E, -mL0)) : 0.f;
            float p01 = ((wA0 >> (bbA+1)) & 1u) ? ex2(fmaf(sacc[nfA][1], LOG2E, -mL0)) : 0.f;
            float p02 = ((wA1 >> bbA) & 1u)     ? ex2(fmaf(sacc[nfA][2], LOG2E, -mL1)) : 0.f;
            float p03 = ((wA1 >> (bbA+1)) & 1u) ? ex2(fmaf(sacc[nfA][3], LOG2E, -mL1)) : 0.f;
            float p10 = ((wB0 >> bbB) & 1u)     ? ex2(fmaf(sacc[nfB][0], LOG2E, -mL0)) : 0.f;
            float p11 = ((wB0 >> (bbB+1)) & 1u) ? ex2(fmaf(sacc[nfB][1], LOG2E, -mL0)) : 0.f;
            float p12 = ((wB1 >> bbB) & 1u)     ? ex2(fmaf(sacc[nfB][2], LOG2E, -mL1)) : 0.f;
            float p13 = ((wB1 >> (bbB+1)) & 1u) ? ex2(fmaf(sacc[nfB][3], LOG2E, -mL1)) : 0.f;
            __half2 h0 = __floats2half2_rn(p00, p01);   // a0: row g,   k-lo
            __half2 h1 = __floats2half2_rn(p02, p03);   // a1: row g+8, k-lo
            __half2 h2 = __floats2half2_rn(p10, p11);   // a2: row g,   k-hi
            __half2 h3 = __floats2half2_rn(p12, p13);   // a3: row g+8, k-hi
            pa[k2][0] = *(uint32_t*)&h0; pa[k2][1] = *(uint32_t*)&h1;
            pa[k2][2] = *(uint32_t*)&h2; pa[k2][3] = *(uint32_t*)&h3;
            float2 f0 = __half22float2(h0), f2 = __half22float2(h2);
            float2 f1 = __half22float2(h1), f3 = __half22float2(h3);
            rs0 += (f0.x + f0.y) + (f2.x + f2.y);
            rs1 += (f1.x + f1.y) + (f3.x + f3.y);
        }

        // ---- GEMM-A: O += P * (Vh + Vl), B via ldmatrix.trans ----
        {
            const int brow  = (((lane >> 3) & 1) << 3) + (lane & 7);
            const int bcolb = (lane >> 4) << 3;
            #pragma unroll
            for (int kf = 0; kf < 8; ++kf) {
                uint32_t bv[8][2];
                #pragma unroll
                for (int j = 0; j < 4; ++j) {
                    uint32_t r4[4];
                    ldsm4t(r4, sbase + ((uint32_t)(SM_KH + ((kf << 4) + brow) * SQ
                                                   + (j << 4) + bcolb) << 1));
                    bv[2*j][0] = r4[0]; bv[2*j][1] = r4[1];
                    bv[2*j+1][0] = r4[2]; bv[2*j+1][1] = r4[3];
                }
                #pragma unroll
                for (int nf = 0; nf < 8; ++nf) mma16816(oacc[nf], pa[kf], bv[nf]);
                #pragma unroll
                for (int j = 0; j < 4; ++j) {
                    uint32_t r4[4];
                    ldsm4t(r4, sbase + ((uint32_t)(SM_KL + ((kf << 4) + brow) * SQ
                                                   + (j << 4) + bcolb) << 1));
                    bv[2*j][0] = r4[0]; bv[2*j][1] = r4[1];
                    bv[2*j+1][0] = r4[2]; bv[2*j+1][1] = r4[3];
                }
                #pragma unroll
                for (int nf = 0; nf < 8; ++nf) mma16816(oacc[nf], pa[kf], bv[nf]);
            }
        }
    }

    // ---- finalize: rowsum quad-reduce ----
    rs0 += __shfl_xor_sync(0xffffffffu, rs0, 1);
    rs0 += __shfl_xor_sync(0xffffffffu, rs0, 2);
    rs1 += __shfl_xor_sync(0xffffffffu, rs1, 1);
    rs1 += __shfl_xor_sync(0xffffffffu, rs1, 2);
    float inv0 = 1.f / rs0, inv1 = 1.f / rs1;

    if (LAYER == 1) {
        int h = bh & (H_ - 1);
        int b = bh >> 2;
        size_t rbase = ((size_t)b * N_ + grow0) * HD_ + h * D_;
        #pragma unroll
        for (int nf = 0; nf < 8; ++nf) {
            int c = (nf << 3) + (tg << 1);
            float b0v = bias[h * D_ + c], b1v = bias[h * D_ + c + 1];
            float2 v0, v1;
            v0.x = lrelu(fmaf(oacc[nf][0], inv0, b0v));
            v0.y = lrelu(fmaf(oacc[nf][1], inv0, b1v));
            v1.x = lrelu(fmaf(oacc[nf][2], inv1, b0v));
            v1.y = lrelu(fmaf(oacc[nf][3], inv1, b1v));
            *(float2*)&g_z[rbase + c]            = v0;
            *(float2*)&g_z[rbase + 8 * HD_ + c]  = v1;
        }
    } else {
        float v0[16], v1[16];
        float s0 = 0.f, s1 = 0.f;
        #pragma unroll
        for (int nf = 0; nf < 8; ++nf) {
            int c = (nf << 3) + (tg << 1);
            float b0v = bias[c], b1v = bias[c + 1];
            float a;
            a = lrelu(fmaf(oacc[nf][0], inv0, b0v)); v0[2*nf]   = a; s0 += a;
            a = lrelu(fmaf(oacc[nf][1], inv0, b1v)); v0[2*nf+1] = a; s0 += a;
            a = lrelu(fmaf(oacc[nf][2], inv1, b0v)); v1[2*nf]   = a; s1 += a;
            a = lrelu(fmaf(oacc[nf][3], inv1, b1v)); v1[2*nf+1] = a; s1 += a;
        }
        s0 += __shfl_xor_sync(0xffffffffu, s0, 1);
        s0 += __shfl_xor_sync(0xffffffffu, s0, 2);
        s1 += __shfl_xor_sync(0xffffffffu, s1, 1);
        s1 += __shfl_xor_sync(0xffffffffu, s1, 2);
        float mu0 = s0 * (1.f / 64.f), mu1 = s1 * (1.f / 64.f);
        float q0 = 0.f, q1 = 0.f;
        #pragma unroll
        for (int i = 0; i < 16; ++i) {
            float u0 = v0[i] - mu0; q0 += u0 * u0;
            float u1 = v1[i] - mu1; q1 += u1 * u1;
        }
        q0 += __shfl_xor_sync(0xffffffffu, q0, 1);
        q0 += __shfl_xor_sync(0xffffffffu, q0, 2);
        q1 += __shfl_xor_sync(0xffffffffu, q1, 1);
        q1 += __shfl_xor_sync(0xffffffffu, q1, 2);
        float rstd0 = rsqrtf(q0 * (1.f / 64.f) + 1e-5f);
        float rstd1 = rsqrtf(q1 * (1.f / 64.f) + 1e-5f);
        float* od0 = outp + ((size_t)bh * N_ + grow0) * D_;
        float* od1 = od0 + 8 * D_;
        #pragma unroll
        for (int nf = 0; nf < 8; ++nf) {
            int c = (nf << 3) + (tg << 1);
            float ga0 = gamma[c], ga1 = gamma[c + 1];
            float be0 = beta[c],  be1 = beta[c + 1];
            float2 w0, w1;
            w0.x = (v0[2*nf]   - mu0) * rstd0 * ga0 + be0;
            w0.y = (v0[2*nf+1] - mu0) * rstd0 * ga1 + be1;
            w1.x = (v1[2*nf]   - mu1) * rstd1 * ga0 + be0;
            w1.y = (v1[2*nf+1] - mu1) * rstd1 * ga1 + be1;
            *(float2*)&od0[c] = w0;
            *(float2*)&od1[c] = w1;
        }
    }
}

// ---------------- launch -----------------------------------------------------
extern "C" void kernel_launch(void* const* d_in, const int* in_sizes, int n_in,
                              void* d_out, int out_size) {
    const float* x     = (const float*)d_in[0];
    const int*   graph = (const int*)  d_in[1];
    const float* Wh    = (const float*)d_in[2];
    const float* bh    = (const float*)d_in[3];
    const float* Wo    = (const float*)d_in[4];
    const float* bo    = (const float*)d_in[5];
    const float* gamma = (const float*)d_in[6];
    const float* beta  = (const float*)d_in[7];
    float* out = (float*)d_out;

    cudaFuncSetAttribute(attn_mma<1>, cudaFuncAttributeMaxDynamicSharedMemorySize, SMEM_ATT);
    cudaFuncSetAttribute(attn_mma<2>, cudaFuncAttributeMaxDynamicSharedMemorySize, SMEM_ATT);

    build_mask_kernel<<<(N_ * NW_) / 8, 256>>>(graph);
    proj1_kernel<<<(B_ * N_) / 64, 256>>>(x, Wh);
    attn_mma<1><<<dim3(B_ * H_, N_ / 128), 256, SMEM_ATT>>>(bh, nullptr, nullptr, nullptr);
    proj2_kernel<<<(B_ * N_) / 64, 256>>>(Wo);
    attn_mma<2><<<dim3(B_, N_ / 128), 256, SMEM_ATT>>>(bo, gamma, beta, out);
}

// round 8
// speedup vs baseline: 11.9762x; 1.1433x over previous
#include <cuda_runtime.h>
#include <cuda_fp16.h>
#include <cstdint>

// Problem shape (fixed for this registry entry)
#define B_  8
#define N_  2048
#define C_  64
#define H_  4
#define D_  64
#define HD_ 256          // H*D
#define NW_ (N_/32)      // mask words per row = 64
#define LOG2E 1.4426950408889634f

// ---------------- scratch (device globals: no allocation allowed) -----------
__device__ __half  g_hH [B_*H_*N_*D_];    // layer1 features, f16 hi
__device__ __half  g_hL [B_*H_*N_*D_];    // layer1 features, f16 lo (residual)
__device__ __half  g_h2H[B_*N_*D_];       // layer2 features hi
__device__ __half  g_h2L[B_*N_*D_];       // layer2 features lo
__device__ float    g_z  [B_*N_*HD_];     // concat+lrelu of layer-1 output
__device__ unsigned g_maskT[NW_*N_];      // transposed bitmask [w][n]

__device__ __forceinline__ float ex2(float x) {
    float y;
    asm("ex2.approx.f32 %0, %1;" : "=f"(y) : "f"(x));
    return y;
}
__device__ __forceinline__ uint32_t smem_u32(const void* p) {
    uint32_t a;
    asm("{ .reg .u64 t; cvta.to.shared.u64 t, %1; cvt.u32.u64 %0, t; }" : "=r"(a) : "l"(p));
    return a;
}
__device__ __forceinline__ void cp16(uint32_t saddr, const void* g) {
    asm volatile("cp.async.ca.shared.global [%0], [%1], 16;"
                 :: "r"(saddr), "l"(__cvta_generic_to_global(g)));
}
__device__ __forceinline__ void ldsm4(uint32_t r[4], uint32_t addr) {
    asm volatile("ldmatrix.sync.aligned.m8n8.x4.shared.b16 {%0,%1,%2,%3}, [%4];"
                 : "=r"(r[0]), "=r"(r[1]), "=r"(r[2]), "=r"(r[3]) : "r"(addr));
}
__device__ __forceinline__ void ldsm4t(uint32_t r[4], uint32_t addr) {
    asm volatile("ldmatrix.sync.aligned.m8n8.x4.trans.shared.b16 {%0,%1,%2,%3}, [%4];"
                 : "=r"(r[0]), "=r"(r[1]), "=r"(r[2]), "=r"(r[3]) : "r"(addr));
}
__device__ __forceinline__ void mma16816(float d[4], const uint32_t a[4], const uint32_t b[2]) {
    asm volatile("mma.sync.aligned.m16n8k16.row.col.f32.f16.f16.f32 "
                 "{%0,%1,%2,%3}, {%4,%5,%6,%7}, {%8,%9}, {%0,%1,%2,%3};"
                 : "+f"(d[0]), "+f"(d[1]), "+f"(d[2]), "+f"(d[3])
                 : "r"(a[0]), "r"(a[1]), "r"(a[2]), "r"(a[3]), "r"(b[0]), "r"(b[1]));
}
__device__ __forceinline__ float lrelu(float a) { return a > 0.f ? a : 0.2f * a; }

__device__ __forceinline__ void split_store(__half* dH, __half* dL, size_t idx,
                                            float v0, float v1) {
    __half h0 = __float2half_rn(v0), h1 = __float2half_rn(v1);
    __half l0 = __float2half_rn(v0 - __half2float(h0));
    __half l1 = __float2half_rn(v1 - __half2float(h1));
    *(__half2*)&dH[idx] = __halves2half2(h0, h1);
    *(__half2*)&dL[idx] = __halves2half2(l0, l1);
}

// ---------------- mask build ------------------------------------------------
__global__ void build_mask_kernel(const int* __restrict__ graph) {
    int gwarp = (blockIdx.x * blockDim.x + threadIdx.x) >> 5;
    int lane  = threadIdx.x & 31;
    if (gwarp >= N_ * NW_) return;
    int n = gwarp >> 6;
    int w = gwarp & (NW_ - 1);
    int m = w * 32 + lane;
    bool bit = (graph[(size_t)n * N_ + m] != 0) || (m == n);
    unsigned word = __ballot_sync(0xffffffffu, bit);
    if (lane == 0) g_maskT[w * N_ + n] = word;
}

// ---------------- proj1 -----------------------------------------------------
__global__ void proj1_kernel(const float* __restrict__ x,
                             const float* __restrict__ Wh) {
    __shared__ float xs[64][65];
    __shared__ float ws[64][65];
    int t    = threadIdx.x;
    int row0 = blockIdx.x * 64;
    for (int i = t; i < 64 * 64; i += 256) {
        int r = i >> 6, c = i & 63;
        xs[r][c] = x[(size_t)(row0 + r) * C_ + c];
    }
    int d0 = (t & 15) * 4;
    int r0 = (t >> 4) * 4;
    int b     = row0 >> 11;
    int nbase = row0 & (N_ - 1);
    for (int h = 0; h < H_; ++h) {
        __syncthreads();
        for (int i = t; i < 64 * 64; i += 256) {
            int r = i >> 6, c = i & 63;
            ws[r][c] = Wh[((size_t)h * D_ + r) * C_ + c];
        }
        __syncthreads();
        float acc[4][4] = {};
        #pragma unroll 8
        for (int c = 0; c < 64; ++c) {
            float xv[4], wv[4];
            #pragma unroll
            for (int i = 0; i < 4; ++i) { xv[i] = xs[r0 + i][c]; wv[i] = ws[d0 + i][c]; }
            #pragma unroll
            for (int i = 0; i < 4; ++i)
                #pragma unroll
                for (int j = 0; j < 4; ++j)
                    acc[i][j] += xv[i] * wv[j];
        }
        #pragma unroll
        for (int i = 0; i < 4; ++i) {
            size_t base = (((size_t)(b * H_ + h) * N_) + nbase + r0 + i) * D_ + d0;
            split_store(g_hH, g_hL, base,     acc[i][0], acc[i][1]);
            split_store(g_hH, g_hL, base + 2, acc[i][2], acc[i][3]);
        }
        __syncthreads();
    }
}

// ---------------- proj2 -----------------------------------------------------
__global__ void proj2_kernel(const float* __restrict__ Wo) {
    __shared__ float zs[64][65];
    __shared__ float ws[64][65];
    int t    = threadIdx.x;
    int row0 = blockIdx.x * 64;
    int d0 = (t & 15) * 4;
    int r0 = (t >> 4) * 4;
    float acc[4][4] = {};
    for (int kc = 0; kc < 4; ++kc) {
        __syncthreads();
        for (int i = t; i < 64 * 64; i += 256) {
            int r = i >> 6, c = i & 63;
            zs[r][c] = g_z[(size_t)(row0 + r) * HD_ + kc * 64 + c];
            ws[r][c] = Wo[(size_t)r * HD_ + kc * 64 + c];
        }
        __syncthreads();
        #pragma unroll 8
        for (int c = 0; c < 64; ++c) {
            float xv[4], wv[4];
            #pragma unroll
            for (int i = 0; i < 4; ++i) { xv[i] = zs[r0 + i][c]; wv[i] = ws[d0 + i][c]; }
            #pragma unroll
            for (int i = 0; i < 4; ++i)
                #pragma unroll
                for (int j = 0; j < 4; ++j)
                    acc[i][j] += xv[i] * wv[j];
        }
    }
    #pragma unroll
    for (int i = 0; i < 4; ++i) {
        size_t base = (size_t)(row0 + r0 + i) * D_ + d0;
        split_store(g_h2H, g_h2L, base,     acc[i][0], acc[i][1]);
        split_store(g_h2H, g_h2L, base + 2, acc[i][2], acc[i][3]);
    }
}

// ================= HMMA flash attention, 4 warps / 64 rows, cp.async ========
// Warp w owns query rows 16w..16w+15 of a 64-row block. KV tile = 128 cols,
// double-buffered via cp.async. S = QhKh+QhKl+QlKh, P f16, O = P(Vh+Vl).
#define SQ 72                          // smem row stride in halves
// half-offsets: QH[64][72], QL[64][72], then 2 K buffers of (KH+KL)[128][72]
#define SM_QH 0
#define SM_QL 4608
#define SM_K  9216
#define KBUF_HALVES 18432              // KH (9216) + KL (9216)
#define SMEM_ATT ((9216 + 2 * KBUF_HALVES) * 2)   // 92160 bytes

template <int LAYER>
__global__ void __launch_bounds__(128, 2)
attn_mma(const float* __restrict__ bias,
         const float* __restrict__ gamma,
         const float* __restrict__ beta,
         float* __restrict__ outp) {
    extern __shared__ __half smh[];
    const int t    = threadIdx.x;
    const int wid  = t >> 5;            // 0..3
    const int lane = t & 31;
    const int g    = lane >> 2;
    const int tg   = lane & 3;
    const int wr0  = wid << 4;
    const int bh   = blockIdx.x;
    const int row0 = blockIdx.y << 6;   // 64 query rows per block
    const __half* hH = (LAYER == 1 ? g_hH : g_h2H) + (size_t)bh * (N_ * D_);
    const __half* hL = (LAYER == 1 ? g_hL : g_h2L) + (size_t)bh * (N_ * D_);
    const uint32_t sbase = smem_u32(smh);

    // ---- stage Q (64 rows) hi+lo via plain loads ----
    {
        const uint4* sH = (const uint4*)(hH + (size_t)row0 * D_);
        const uint4* sL = (const uint4*)(hL + (size_t)row0 * D_);
        #pragma unroll
        for (int i = 0; i < 4; ++i) {
            int idx = t + (i << 7);            // 0..511
            int r = idx >> 3, c8 = (idx & 7) << 3;
            *(uint4*)&smh[SM_QH + r * SQ + c8] = sH[idx];
            *(uint4*)&smh[SM_QL + r * SQ + c8] = sL[idx];
        }
    }

    // ---- prefetch K tile 0 into buffer 0 ----
    {
        const uint4* sH = (const uint4*)hH;
        const uint4* sL = (const uint4*)hL;
        uint32_t kb = sbase + SM_K * 2;
        #pragma unroll
        for (int i = 0; i < 8; ++i) {
            int idx = t + (i << 7);            // 0..1023
            int r = idx >> 3, c8 = (idx & 7) << 3;
            uint32_t so = (uint32_t)(r * SQ + c8) << 1;
            cp16(kb + so, sH + idx);
            cp16(kb + (9216 << 1) + so, sL + idx);
        }
        asm volatile("cp.async.commit_group;" ::: "memory");
    }
    __syncthreads();

    // ---- preload Q A-frags ----
    uint32_t qh[4][4], ql[4][4];
    {
        int arow  = wr0 + (lane & 15);
        int acolb = (lane >> 4) << 3;
        #pragma unroll
        for (int kf = 0; kf < 4; ++kf) {
            ldsm4(qh[kf], sbase + ((uint32_t)(SM_QH + arow * SQ + (kf << 4) + acolb) << 1));
            ldsm4(ql[kf], sbase + ((uint32_t)(SM_QL + arow * SQ + (kf << 4) + acolb) << 1));
        }
    }

    float oacc[8][4];
    #pragma unroll
    for (int i = 0; i < 8; ++i)
        #pragma unroll
        for (int j = 0; j < 4; ++j) oacc[i][j] = 0.f;
    float rs0 = 0.f, rs1 = 0.f, mr0 = -1e30f, mr1 = -1e30f;
    const int grow0 = row0 + wr0 + g;

    #pragma unroll 1
    for (int tile = 0; tile < N_ / 128; ++tile) {
        const int buf = tile & 1;
        // ---- prefetch next tile into other buffer ----
        if (tile + 1 < N_ / 128) {
            const uint4* sH = (const uint4*)(hH + (size_t)(tile + 1) * (128 * D_));
            const uint4* sL = (const uint4*)(hL + (size_t)(tile + 1) * (128 * D_));
            uint32_t kb = sbase + (uint32_t)(SM_K + (buf ^ 1) * KBUF_HALVES) * 2;
            #pragma unroll
            for (int i = 0; i < 8; ++i) {
                int idx = t + (i << 7);
                int r = idx >> 3, c8 = (idx & 7) << 3;
                uint32_t so = (uint32_t)(r * SQ + c8) << 1;
                cp16(kb + so, sH + idx);
                cp16(kb + (9216 << 1) + so, sL + idx);
            }
            asm volatile("cp.async.commit_group;" ::: "memory");
            asm volatile("cp.async.wait_group 1;" ::: "memory");
        } else {
            asm volatile("cp.async.wait_group 0;" ::: "memory");
        }
        unsigned mw0[4], mw1[4];
        #pragma unroll
        for (int w = 0; w < 4; ++w) {
            mw0[w] = g_maskT[(size_t)((tile << 2) + w) * N_ + grow0];
            mw1[w] = g_maskT[(size_t)((tile << 2) + w) * N_ + grow0 + 8];
        }
        __syncthreads();

        const uint32_t kbH = sbase + (uint32_t)(SM_K + buf * KBUF_HALVES) * 2;
        const uint32_t kbL = kbH + (9216u << 1);

        // ---- GEMM-S ----
        float sacc[16][4];
        #pragma unroll
        for (int i = 0; i < 16; ++i)
            #pragma unroll
            for (int j = 0; j < 4; ++j) sacc[i][j] = 0.f;
        {
            const int brow = ((lane >> 4) << 3) + (lane & 7);
            const int bcol = ((lane >> 3) & 1) << 3;
            #pragma unroll
            for (int kf = 0; kf < 4; ++kf) {
                #pragma unroll
                for (int hseg = 0; hseg < 2; ++hseg) {
                    uint32_t bfr[8][2];
                    #pragma unroll
                    for (int j = 0; j < 4; ++j) {
                        uint32_t r4[4];
                        int jj = hseg * 4 + j;
                        ldsm4(r4, kbH + ((uint32_t)(((jj << 4) + brow) * SQ
                                                    + (kf << 4) + bcol) << 1));
                        bfr[2*j][0] = r4[0]; bfr[2*j][1] = r4[1];
                        bfr[2*j+1][0] = r4[2]; bfr[2*j+1][1] = r4[3];
                    }
                    #pragma unroll
                    for (int nf = 0; nf < 8; ++nf) mma16816(sacc[hseg*8+nf], qh[kf], bfr[nf]);
                    #pragma unroll
                    for (int nf = 0; nf < 8; ++nf) mma16816(sacc[hseg*8+nf], ql[kf], bfr[nf]);
                    #pragma unroll
                    for (int j = 0; j < 4; ++j) {
                        uint32_t r4[4];
                        int jj = hseg * 4 + j;
                        ldsm4(r4, kbL + ((uint32_t)(((jj << 4) + brow) * SQ
                                                    + (kf << 4) + bcol) << 1));
                        bfr[2*j][0] = r4[0]; bfr[2*j][1] = r4[1];
                        bfr[2*j+1][0] = r4[2]; bfr[2*j+1][1] = r4[3];
                    }
                    #pragma unroll
                    for (int nf = 0; nf < 8; ++nf) mma16816(sacc[hseg*8+nf], qh[kf], bfr[nf]);
                }
            }
        }

        // ---- masked online softmax; P -> A-frags in registers ----
        float m0 = -1e30f, m1 = -1e30f;
        #pragma unroll
        for (int nf = 0; nf < 16; ++nf) {
            unsigned w0 = mw0[nf >> 2], w1 = mw1[nf >> 2];
            int bb = ((nf & 3) << 3) + (tg << 1);
            m0 = fmaxf(m0, ((w0 >> bb) & 1u)       ? sacc[nf][0] : -1e30f);
            m0 = fmaxf(m0, ((w0 >> (bb + 1)) & 1u) ? sacc[nf][1] : -1e30f);
            m1 = fmaxf(m1, ((w1 >> bb) & 1u)       ? sacc[nf][2] : -1e30f);
            m1 = fmaxf(m1, ((w1 >> (bb + 1)) & 1u) ? sacc[nf][3] : -1e30f);
        }
        m0 = fmaxf(m0, __shfl_xor_sync(0xffffffffu, m0, 1));
        m0 = fmaxf(m0, __shfl_xor_sync(0xffffffffu, m0, 2));
        m1 = fmaxf(m1, __shfl_xor_sync(0xffffffffu, m1, 1));
        m1 = fmaxf(m1, __shfl_xor_sync(0xffffffffu, m1, 2));
        float mn0 = fmaxf(mr0, m0), mn1 = fmaxf(mr1, m1);
        float al0 = ex2((mr0 - mn0) * LOG2E), al1 = ex2((mr1 - mn1) * LOG2E);
        mr0 = mn0; mr1 = mn1;
        rs0 *= al0; rs1 *= al1;
        #pragma unroll
        for (int nf = 0; nf < 8; ++nf) {
            oacc[nf][0] *= al0; oacc[nf][1] *= al0;
            oacc[nf][2] *= al1; oacc[nf][3] *= al1;
        }
        const float mL0 = mn0 * LOG2E, mL1 = mn1 * LOG2E;
        uint32_t pa[8][4];
        #pragma unroll
        for (int k2 = 0; k2 < 8; ++k2) {
            int nfA = k2 << 1, nfB = nfA + 1;
            unsigned wA0 = mw0[nfA >> 2], wA1 = mw1[nfA >> 2];
            unsigned wB0 = mw0[nfB >> 2], wB1 = mw1[nfB >> 2];
            int bbA = ((nfA & 3) << 3) + (tg << 1);
            int bbB = ((nfB & 3) << 3) + (tg << 1);
            float p00 = ((wA0 >> bbA) & 1u)     ? ex2(fmaf(sacc[nfA][0], LOG2E, -mL0)) : 0.f;
            float p01 = ((wA0 >> (bbA+1)) & 1u) ? ex2(fmaf(sacc[nfA][1], LOG2E, -mL0)) : 0.f;
            float p02 = ((wA1 >> bbA) & 1u)     ? ex2(fmaf(sacc[nfA][2], LOG2E, -mL1)) : 0.f;
            float p03 = ((wA1 >> (bbA+1)) & 1u) ? ex2(fmaf(sacc[nfA][3], LOG2E, -mL1)) : 0.f;
            float p10 = ((wB0 >> bbB) & 1u)     ? ex2(fmaf(sacc[nfB][0], LOG2E, -mL0)) : 0.f;
            float p11 = ((wB0 >> (bbB+1)) & 1u) ? ex2(fmaf(sacc[nfB][1], LOG2E, -mL0)) : 0.f;
            float p12 = ((wB1 >> bbB) & 1u)     ? ex2(fmaf(sacc[nfB][2], LOG2E, -mL1)) : 0.f;
            float p13 = ((wB1 >> (bbB+1)) & 1u) ? ex2(fmaf(sacc[nfB][3], LOG2E, -mL1)) : 0.f;
            __half2 h0 = __floats2half2_rn(p00, p01);
            __half2 h1 = __floats2half2_rn(p02, p03);
            __half2 h2 = __floats2half2_rn(p10, p11);
            __half2 h3 = __floats2half2_rn(p12, p13);
            pa[k2][0] = *(uint32_t*)&h0; pa[k2][1] = *(uint32_t*)&h1;
            pa[k2][2] = *(uint32_t*)&h2; pa[k2][3] = *(uint32_t*)&h3;
            float2 f0 = __half22float2(h0), f2 = __half22float2(h2);
            float2 f1 = __half22float2(h1), f3 = __half22float2(h3);
            rs0 += (f0.x + f0.y) + (f2.x + f2.y);
            rs1 += (f1.x + f1.y) + (f3.x + f3.y);
        }

        // ---- GEMM-A: O += P * (Vh + Vl) ----
        {
            const int brow  = (((lane >> 3) & 1) << 3) + (lane & 7);
            const int bcolb = (lane >> 4) << 3;
            #pragma unroll
            for (int kf = 0; kf < 8; ++kf) {
                uint32_t bv[8][2];
                #pragma unroll
                for (int j = 0; j < 4; ++j) {
                    uint32_t r4[4];
                    ldsm4t(r4, kbH + ((uint32_t)(((kf << 4) + brow) * SQ
                                                 + (j << 4) + bcolb) << 1));
                    bv[2*j][0] = r4[0]; bv[2*j][1] = r4[1];
                    bv[2*j+1][0] = r4[2]; bv[2*j+1][1] = r4[3];
                }
                #pragma unroll
                for (int nf = 0; nf < 8; ++nf) mma16816(oacc[nf], pa[kf], bv[nf]);
                #pragma unroll
                for (int j = 0; j < 4; ++j) {
                    uint32_t r4[4];
                    ldsm4t(r4, kbL + ((uint32_t)(((kf << 4) + brow) * SQ
                                                 + (j << 4) + bcolb) << 1));
                    bv[2*j][0] = r4[0]; bv[2*j][1] = r4[1];
                    bv[2*j+1][0] = r4[2]; bv[2*j+1][1] = r4[3];
                }
                #pragma unroll
                for (int nf = 0; nf < 8; ++nf) mma16816(oacc[nf], pa[kf], bv[nf]);
            }
        }
        __syncthreads();   // all warps done with this buffer before it is refilled
    }

    // ---- finalize ----
    rs0 += __shfl_xor_sync(0xffffffffu, rs0, 1);
    rs0 += __shfl_xor_sync(0xffffffffu, rs0, 2);
    rs1 += __shfl_xor_sync(0xffffffffu, rs1, 1);
    rs1 += __shfl_xor_sync(0xffffffffu, rs1, 2);
    float inv0 = 1.f / rs0, inv1 = 1.f / rs1;

    if (LAYER == 1) {
        int h = bh & (H_ - 1);
        int b = bh >> 2;
        size_t rbase = ((size_t)b * N_ + grow0) * HD_ + h * D_;
        #pragma unroll
        for (int nf = 0; nf < 8; ++nf) {
            int c = (nf << 3) + (tg << 1);
            float b0v = bias[h * D_ + c], b1v = bias[h * D_ + c + 1];
            float2 v0, v1;
            v0.x = lrelu(fmaf(oacc[nf][0], inv0, b0v));
            v0.y = lrelu(fmaf(oacc[nf][1], inv0, b1v));
            v1.x = lrelu(fmaf(oacc[nf][2], inv1, b0v));
            v1.y = lrelu(fmaf(oacc[nf][3], inv1, b1v));
            *(float2*)&g_z[rbase + c]           = v0;
            *(float2*)&g_z[rbase + 8 * HD_ + c] = v1;
        }
    } else {
        float v0[16], v1[16];
        float s0 = 0.f, s1 = 0.f;
        #pragma unroll
        for (int nf = 0; nf < 8; ++nf) {
            int c = (nf << 3) + (tg << 1);
            float b0v = bias[c], b1v = bias[c + 1];
            float a;
            a = lrelu(fmaf(oacc[nf][0], inv0, b0v)); v0[2*nf]   = a; s0 += a;
            a = lrelu(fmaf(oacc[nf][1], inv0, b1v)); v0[2*nf+1] = a; s0 += a;
            a = lrelu(fmaf(oacc[nf][2], inv1, b0v)); v1[2*nf]   = a; s1 += a;
            a = lrelu(fmaf(oacc[nf][3], inv1, b1v)); v1[2*nf+1] = a; s1 += a;
        }
        s0 += __shfl_xor_sync(0xffffffffu, s0, 1);
        s0 += __shfl_xor_sync(0xffffffffu, s0, 2);
        s1 += __shfl_xor_sync(0xffffffffu, s1, 1);
        s1 += __shfl_xor_sync(0xffffffffu, s1, 2);
        float mu0 = s0 * (1.f / 64.f), mu1 = s1 * (1.f / 64.f);
        float q0 = 0.f, q1 = 0.f;
        #pragma unroll
        for (int i = 0; i < 16; ++i) {
            float u0 = v0[i] - mu0; q0 += u0 * u0;
            float u1 = v1[i] - mu1; q1 += u1 * u1;
        }
        q0 += __shfl_xor_sync(0xffffffffu, q0, 1);
        q0 += __shfl_xor_sync(0xffffffffu, q0, 2);
        q1 += __shfl_xor_sync(0xffffffffu, q1, 1);
        q1 += __shfl_xor_sync(0xffffffffu, q1, 2);
        float rstd0 = rsqrtf(q0 * (1.f / 64.f) + 1e-5f);
        float rstd1 = rsqrtf(q1 * (1.f / 64.f) + 1e-5f);
        float* od0 = outp + ((size_t)bh * N_ + grow0) * D_;
        float* od1 = od0 + 8 * D_;
        #pragma unroll
        for (int nf = 0; nf < 8; ++nf) {
            int c = (nf << 3) + (tg << 1);
            float ga0 = gamma[c], ga1 = gamma[c + 1];
            float be0 = beta[c],  be1 = beta[c + 1];
            float2 w0, w1;
            w0.x = (v0[2*nf]   - mu0) * rstd0 * ga0 + be0;
            w0.y = (v0[2*nf+1] - mu0) * rstd0 * ga1 + be1;
            w1.x = (v1[2*nf]   - mu1) * rstd1 * ga0 + be0;
            w1.y = (v1[2*nf+1] - mu1) * rstd1 * ga1 + be1;
            *(float2*)&od0[c] = w0;
            *(float2*)&od1[c] = w1;
        }
    }
}

// ---------------- launch -----------------------------------------------------
extern "C" void kernel_launch(void* const* d_in, const int* in_sizes, int n_in,
                              void* d_out, int out_size) {
    const float* x     = (const float*)d_in[0];
    const int*   graph = (const int*)  d_in[1];
    const float* Wh    = (const float*)d_in[2];
    const float* bh    = (const float*)d_in[3];
    const float* Wo    = (const float*)d_in[4];
    const float* bo    = (const float*)d_in[5];
    const float* gamma = (const float*)d_in[6];
    const float* beta  = (const float*)d_in[7];
    float* out = (float*)d_out;

    cudaFuncSetAttribute(attn_mma<1>, cudaFuncAttributeMaxDynamicSharedMemorySize, SMEM_ATT);
    cudaFuncSetAttribute(attn_mma<2>, cudaFuncAttributeMaxDynamicSharedMemorySize, SMEM_ATT);

    build_mask_kernel<<<(N_ * NW_) / 8, 256>>>(graph);
    proj1_kernel<<<(B_ * N_) / 64, 256>>>(x, Wh);
    attn_mma<1><<<dim3(B_ * H_, N_ / 64), 128, SMEM_ATT>>>(bh, nullptr, nullptr, nullptr);
    proj2_kernel<<<(B_ * N_) / 64, 256>>>(Wo);
    attn_mma<2><<<dim3(B_, N_ / 64), 128, SMEM_ATT>>>(bo, gamma, beta, out);
}

// round 9
// speedup vs baseline: 12.2500x; 1.0229x over previous
#include <cuda_runtime.h>
#include <cuda_fp16.h>
#include <cstdint>

// Problem shape (fixed for this registry entry)
#define B_  8
#define N_  2048
#define C_  64
#define H_  4
#define D_  64
#define HD_ 256          // H*D
#define NW_ (N_/32)      // mask words per row = 64
#define LOG2E 1.4426950408889634f

// ---------------- scratch (device globals: no allocation allowed) -----------
__device__ __half  g_hH [B_*H_*N_*D_];    // layer1 features, f16 hi
__device__ __half  g_hL [B_*H_*N_*D_];    // layer1 features, f16 lo (residual)
__device__ __half  g_h2H[B_*N_*D_];       // layer2 features hi
__device__ __half  g_h2L[B_*N_*D_];       // layer2 features lo
__device__ float    g_z  [B_*N_*HD_];     // concat+lrelu of layer-1 output
__device__ unsigned g_maskT[NW_*N_];      // transposed bitmask [w][n]

__device__ __forceinline__ float ex2(float x) {
    float y;
    asm("ex2.approx.f32 %0, %1;" : "=f"(y) : "f"(x));
    return y;
}
__device__ __forceinline__ uint32_t smem_u32(const void* p) {
    uint32_t a;
    asm("{ .reg .u64 t; cvta.to.shared.u64 t, %1; cvt.u32.u64 %0, t; }" : "=r"(a) : "l"(p));
    return a;
}
__device__ __forceinline__ void cp16(uint32_t saddr, const void* g) {
    asm volatile("cp.async.ca.shared.global [%0], [%1], 16;"
                 :: "r"(saddr), "l"(__cvta_generic_to_global(g)));
}
__device__ __forceinline__ void ldsm4(uint32_t r[4], uint32_t addr) {
    asm volatile("ldmatrix.sync.aligned.m8n8.x4.shared.b16 {%0,%1,%2,%3}, [%4];"
                 : "=r"(r[0]), "=r"(r[1]), "=r"(r[2]), "=r"(r[3]) : "r"(addr));
}
__device__ __forceinline__ void ldsm4t(uint32_t r[4], uint32_t addr) {
    asm volatile("ldmatrix.sync.aligned.m8n8.x4.trans.shared.b16 {%0,%1,%2,%3}, [%4];"
                 : "=r"(r[0]), "=r"(r[1]), "=r"(r[2]), "=r"(r[3]) : "r"(addr));
}
__device__ __forceinline__ void mma16816(float d[4], const uint32_t a[4], const uint32_t b[2]) {
    asm volatile("mma.sync.aligned.m16n8k16.row.col.f32.f16.f16.f32 "
                 "{%0,%1,%2,%3}, {%4,%5,%6,%7}, {%8,%9}, {%0,%1,%2,%3};"
                 : "+f"(d[0]), "+f"(d[1]), "+f"(d[2]), "+f"(d[3])
                 : "r"(a[0]), "r"(a[1]), "r"(a[2]), "r"(a[3]), "r"(b[0]), "r"(b[1]));
}
__device__ __forceinline__ float lrelu(float a) { return a > 0.f ? a : 0.2f * a; }

__device__ __forceinline__ void split_store(__half* dH, __half* dL, size_t idx,
                                            float v0, float v1) {
    __half h0 = __float2half_rn(v0), h1 = __float2half_rn(v1);
    __half l0 = __float2half_rn(v0 - __half2float(h0));
    __half l1 = __float2half_rn(v1 - __half2float(h1));
    *(__half2*)&dH[idx] = __halves2half2(h0, h1);
    *(__half2*)&dL[idx] = __halves2half2(l0, l1);
}

// ---------------- mask build ------------------------------------------------
__global__ void build_mask_kernel(const int* __restrict__ graph) {
    int gwarp = (blockIdx.x * blockDim.x + threadIdx.x) >> 5;
    int lane  = threadIdx.x & 31;
    if (gwarp >= N_ * NW_) return;
    int n = gwarp >> 6;
    int w = gwarp & (NW_ - 1);
    int m = w * 32 + lane;
    bool bit = (graph[(size_t)n * N_ + m] != 0) || (m == n);
    unsigned word = __ballot_sync(0xffffffffu, bit);
    if (lane == 0) g_maskT[w * N_ + n] = word;
}

// ---------------- proj1: one head per blockIdx.y (grid 256 x 4) -------------
__global__ void proj1_kernel(const float* __restrict__ x,
                             const float* __restrict__ Wh) {
    __shared__ float xs[64][65];
    __shared__ float ws[64][65];
    int t    = threadIdx.x;              // 256 threads
    int row0 = blockIdx.x * 64;          // flattened b*N + n
    int h    = blockIdx.y;
    for (int i = t; i < 64 * 64; i += 256) {
        int r = i >> 6, c = i & 63;
        xs[r][c] = x[(size_t)(row0 + r) * C_ + c];
        ws[r][c] = Wh[((size_t)h * D_ + r) * C_ + c];
    }
    __syncthreads();
    int d0 = (t & 15) * 4;
    int r0 = (t >> 4) * 4;
    int b     = row0 >> 11;
    int nbase = row0 & (N_ - 1);
    float acc[4][4] = {};
    #pragma unroll 8
    for (int c = 0; c < 64; ++c) {
        float xv[4], wv[4];
        #pragma unroll
        for (int i = 0; i < 4; ++i) { xv[i] = xs[r0 + i][c]; wv[i] = ws[d0 + i][c]; }
        #pragma unroll
        for (int i = 0; i < 4; ++i)
            #pragma unroll
            for (int j = 0; j < 4; ++j)
                acc[i][j] += xv[i] * wv[j];
    }
    #pragma unroll
    for (int i = 0; i < 4; ++i) {
        size_t base = (((size_t)(b * H_ + h) * N_) + nbase + r0 + i) * D_ + d0;
        split_store(g_hH, g_hL, base,     acc[i][0], acc[i][1]);
        split_store(g_hH, g_hL, base + 2, acc[i][2], acc[i][3]);
    }
}

// ---------------- proj2: 512 threads, 2x4 micro-tile ------------------------
__global__ void proj2_kernel(const float* __restrict__ Wo) {
    __shared__ float zs[64][65];
    __shared__ float ws[64][65];
    int t    = threadIdx.x;              // 512 threads
    int row0 = blockIdx.x * 64;
    int d0 = (t & 15) * 4;
    int r0 = (t >> 4) * 2;               // 0..62
    float acc[2][4] = {};
    for (int kc = 0; kc < 4; ++kc) {
        __syncthreads();
        for (int i = t; i < 64 * 64; i += 512) {
            int r = i >> 6, c = i & 63;
            zs[r][c] = g_z[(size_t)(row0 + r) * HD_ + kc * 64 + c];
            ws[r][c] = Wo[(size_t)r * HD_ + kc * 64 + c];
        }
        __syncthreads();
        #pragma unroll 8
        for (int c = 0; c < 64; ++c) {
            float xv[2], wv[4];
            xv[0] = zs[r0][c]; xv[1] = zs[r0 + 1][c];
            #pragma unroll
            for (int j = 0; j < 4; ++j) wv[j] = ws[d0 + j][c];
            #pragma unroll
            for (int i = 0; i < 2; ++i)
                #pragma unroll
                for (int j = 0; j < 4; ++j)
                    acc[i][j] += xv[i] * wv[j];
        }
    }
    #pragma unroll
    for (int i = 0; i < 2; ++i) {
        size_t base = (size_t)(row0 + r0 + i) * D_ + d0;
        split_store(g_h2H, g_h2L, base,     acc[i][0], acc[i][1]);
        split_store(g_h2H, g_h2L, base + 2, acc[i][2], acc[i][3]);
    }
}

// ================= HMMA flash attention, 4 warps / 64 rows ===================
// KV tile = 64 cols, 3-deep cp.async ring. S = QhKh+QhKl+QlKh, P f16,
// O = P(Vh+Vl). 3 blocks/SM for tensor-pipe overlap across blocks.
#define SQ 72                          // smem row stride in halves
#define NT 32                          // KV tiles
#define SM_QH 0
#define SM_QL 4608
#define SM_K  9216
#define KBUF_HALVES 9216               // (KH + KL)[64][72]
#define SMEM_ATT ((9216 + 3 * KBUF_HALVES) * 2)   // 73728 bytes

template <int LAYER>
__global__ void __launch_bounds__(128, 3)
attn_mma(const float* __restrict__ bias,
         const float* __restrict__ gamma,
         const float* __restrict__ beta,
         float* __restrict__ outp) {
    extern __shared__ __half smh[];
    const int t    = threadIdx.x;
    const int wid  = t >> 5;            // 0..3
    const int lane = t & 31;
    const int g    = lane >> 2;
    const int tg   = lane & 3;
    const int wr0  = wid << 4;
    const int bh   = blockIdx.x;
    const int row0 = blockIdx.y << 6;   // 64 query rows per block
    const __half* hH = (LAYER == 1 ? g_hH : g_h2H) + (size_t)bh * (N_ * D_);
    const __half* hL = (LAYER == 1 ? g_hL : g_h2L) + (size_t)bh * (N_ * D_);
    const uint32_t sbase = smem_u32(smh);

    // ---- stage Q (64 rows) hi+lo via plain loads ----
    {
        const uint4* sH = (const uint4*)(hH + (size_t)row0 * D_);
        const uint4* sL = (const uint4*)(hL + (size_t)row0 * D_);
        #pragma unroll
        for (int i = 0; i < 4; ++i) {
            int idx = t + (i << 7);            // 0..511
            int r = idx >> 3, c8 = (idx & 7) << 3;
            *(uint4*)&smh[SM_QH + r * SQ + c8] = sH[idx];
            *(uint4*)&smh[SM_QL + r * SQ + c8] = sL[idx];
        }
    }
    // ---- prefetch K tiles 0,1 into ring buffers 0,1 ----
    #pragma unroll
    for (int pt = 0; pt < 2; ++pt) {
        const uint4* sH = (const uint4*)(hH + (size_t)pt * (64 * D_));
        const uint4* sL = (const uint4*)(hL + (size_t)pt * (64 * D_));
        uint32_t kb = sbase + (uint32_t)(SM_K + pt * KBUF_HALVES) * 2;
        #pragma unroll
        for (int i = 0; i < 4; ++i) {
            int idx = t + (i << 7);            // 0..511
            int r = idx >> 3, c8 = (idx & 7) << 3;
            uint32_t so = (uint32_t)(r * SQ + c8) << 1;
            cp16(kb + so, sH + idx);
            cp16(kb + (4608u << 1) + so, sL + idx);
        }
        asm volatile("cp.async.commit_group;" ::: "memory");
    }
    __syncthreads();

    // ---- preload Q A-frags ----
    uint32_t qh[4][4], ql[4][4];
    {
        int arow  = wr0 + (lane & 15);
        int acolb = (lane >> 4) << 3;
        #pragma unroll
        for (int kf = 0; kf < 4; ++kf) {
            ldsm4(qh[kf], sbase + ((uint32_t)(SM_QH + arow * SQ + (kf << 4) + acolb) << 1));
            ldsm4(ql[kf], sbase + ((uint32_t)(SM_QL + arow * SQ + (kf << 4) + acolb) << 1));
        }
    }

    float oacc[8][4];
    #pragma unroll
    for (int i = 0; i < 8; ++i)
        #pragma unroll
        for (int j = 0; j < 4; ++j) oacc[i][j] = 0.f;
    float rs0 = 0.f, rs1 = 0.f, mr0 = -1e30f, mr1 = -1e30f;
    const int grow0 = row0 + wr0 + g;

    int buf = 0;
    #pragma unroll 1
    for (int tile = 0; tile < NT; ++tile) {
        // tile's data (group committed 2 iterations ago) must be complete;
        // at most 1 newer group (tile+1) may stay in flight.
        asm volatile("cp.async.wait_group 1;" ::: "memory");
        __syncthreads();                 // all warps done with buf (tile-1+3 = tile+2's target)
        // ---- prefetch tile+2 into ring slot (tile+2)%3 ----
        {
            int pt = tile + 2;
            if (pt < NT) {
                int pb = buf + 2; if (pb >= 3) pb -= 3;
                const uint4* sH = (const uint4*)(hH + (size_t)pt * (64 * D_));
                const uint4* sL = (const uint4*)(hL + (size_t)pt * (64 * D_));
                uint32_t kb = sbase + (uint32_t)(SM_K + pb * KBUF_HALVES) * 2;
                #pragma unroll
                for (int i = 0; i < 4; ++i) {
                    int idx = t + (i << 7);
                    int r = idx >> 3, c8 = (idx & 7) << 3;
                    uint32_t so = (uint32_t)(r * SQ + c8) << 1;
                    cp16(kb + so, sH + idx);
                    cp16(kb + (4608u << 1) + so, sL + idx);
                }
            }
            asm volatile("cp.async.commit_group;" ::: "memory");   // empty group ok
        }
        unsigned mw0[2], mw1[2];
        #pragma unroll
        for (int w = 0; w < 2; ++w) {
            mw0[w] = g_maskT[(size_t)((tile << 1) + w) * N_ + grow0];
            mw1[w] = g_maskT[(size_t)((tile << 1) + w) * N_ + grow0 + 8];
        }

        const uint32_t kbH = sbase + (uint32_t)(SM_K + buf * KBUF_HALVES) * 2;
        const uint32_t kbL = kbH + (4608u << 1);

        // ---- GEMM-S: sacc[8 nf][4] over 4 kf, 3 split terms ----
        float sacc[8][4];
        #pragma unroll
        for (int i = 0; i < 8; ++i)
            #pragma unroll
            for (int j = 0; j < 4; ++j) sacc[i][j] = 0.f;
        {
            const int brow = ((lane >> 4) << 3) + (lane & 7);
            const int bcol = ((lane >> 3) & 1) << 3;
            #pragma unroll
            for (int kf = 0; kf < 4; ++kf) {
                uint32_t bfr[8][2];
                #pragma unroll
                for (int j = 0; j < 4; ++j) {
                    uint32_t r4[4];
                    ldsm4(r4, kbH + ((uint32_t)(((j << 4) + brow) * SQ
                                                + (kf << 4) + bcol) << 1));
                    bfr[2*j][0] = r4[0]; bfr[2*j][1] = r4[1];
                    bfr[2*j+1][0] = r4[2]; bfr[2*j+1][1] = r4[3];
                }
                #pragma unroll
                for (int nf = 0; nf < 8; ++nf) mma16816(sacc[nf], qh[kf], bfr[nf]);
                #pragma unroll
                for (int nf = 0; nf < 8; ++nf) mma16816(sacc[nf], ql[kf], bfr[nf]);
                #pragma unroll
                for (int j = 0; j < 4; ++j) {
                    uint32_t r4[4];
                    ldsm4(r4, kbL + ((uint32_t)(((j << 4) + brow) * SQ
                                                + (kf << 4) + bcol) << 1));
                    bfr[2*j][0] = r4[0]; bfr[2*j][1] = r4[1];
                    bfr[2*j+1][0] = r4[2]; bfr[2*j+1][1] = r4[3];
                }
                #pragma unroll
                for (int nf = 0; nf < 8; ++nf) mma16816(sacc[nf], qh[kf], bfr[nf]);
            }
        }

        // ---- masked online softmax; P -> A-frags in registers ----
        float m0 = -1e30f, m1 = -1e30f;
        #pragma unroll
        for (int nf = 0; nf < 8; ++nf) {
            unsigned w0 = mw0[nf >> 2], w1 = mw1[nf >> 2];
            int bb = ((nf & 3) << 3) + (tg << 1);
            m0 = fmaxf(m0, ((w0 >> bb) & 1u)       ? sacc[nf][0] : -1e30f);
            m0 = fmaxf(m0, ((w0 >> (bb + 1)) & 1u) ? sacc[nf][1] : -1e30f);
            m1 = fmaxf(m1, ((w1 >> bb) & 1u)       ? sacc[nf][2] : -1e30f);
            m1 = fmaxf(m1, ((w1 >> (bb + 1)) & 1u) ? sacc[nf][3] : -1e30f);
        }
        m0 = fmaxf(m0, __shfl_xor_sync(0xffffffffu, m0, 1));
        m0 = fmaxf(m0, __shfl_xor_sync(0xffffffffu, m0, 2));
        m1 = fmaxf(m1, __shfl_xor_sync(0xffffffffu, m1, 1));
        m1 = fmaxf(m1, __shfl_xor_sync(0xffffffffu, m1, 2));
        float mn0 = fmaxf(mr0, m0), mn1 = fmaxf(mr1, m1);
        float al0 = ex2((mr0 - mn0) * LOG2E), al1 = ex2((mr1 - mn1) * LOG2E);
        mr0 = mn0; mr1 = mn1;
        rs0 *= al0; rs1 *= al1;
        #pragma unroll
        for (int nf = 0; nf < 8; ++nf) {
            oacc[nf][0] *= al0; oacc[nf][1] *= al0;
            oacc[nf][2] *= al1; oacc[nf][3] *= al1;
        }
        const float mL0 = mn0 * LOG2E, mL1 = mn1 * LOG2E;
        uint32_t pa[4][4];
        #pragma unroll
        for (int k2 = 0; k2 < 4; ++k2) {
            int nfA = k2 << 1, nfB = nfA + 1;
            unsigned wA0 = mw0[nfA >> 2], wA1 = mw1[nfA >> 2];
            unsigned wB0 = mw0[nfB >> 2], wB1 = mw1[nfB >> 2];
            int bbA = ((nfA & 3) << 3) + (tg << 1);
            int bbB = ((nfB & 3) << 3) + (tg << 1);
            float p00 = ((wA0 >> bbA) & 1u)     ? ex2(fmaf(sacc[nfA][0], LOG2E, -mL0)) : 0.f;
            float p01 = ((wA0 >> (bbA+1)) & 1u) ? ex2(fmaf(sacc[nfA][1], LOG2E, -mL0)) : 0.f;
            float p02 = ((wA1 >> bbA) & 1u)     ? ex2(fmaf(sacc[nfA][2], LOG2E, -mL1)) : 0.f;
            float p03 = ((wA1 >> (bbA+1)) & 1u) ? ex2(fmaf(sacc[nfA][3], LOG2E, -mL1)) : 0.f;
            float p10 = ((wB0 >> bbB) & 1u)     ? ex2(fmaf(sacc[nfB][0], LOG2E, -mL0)) : 0.f;
            float p11 = ((wB0 >> (bbB+1)) & 1u) ? ex2(fmaf(sacc[nfB][1], LOG2E, -mL0)) : 0.f;
            float p12 = ((wB1 >> bbB) & 1u)     ? ex2(fmaf(sacc[nfB][2], LOG2E, -mL1)) : 0.f;
            float p13 = ((wB1 >> (bbB+1)) & 1u) ? ex2(fmaf(sacc[nfB][3], LOG2E, -mL1)) : 0.f;
            __half2 h0 = __floats2half2_rn(p00, p01);
            __half2 h1 = __floats2half2_rn(p02, p03);
            __half2 h2 = __floats2half2_rn(p10, p11);
            __half2 h3 = __floats2half2_rn(p12, p13);
            pa[k2][0] = *(uint32_t*)&h0; pa[k2][1] = *(uint32_t*)&h1;
            pa[k2][2] = *(uint32_t*)&h2; pa[k2][3] = *(uint32_t*)&h3;
            float2 f0 = __half22float2(h0), f2 = __half22float2(h2);
            float2 f1 = __half22float2(h1), f3 = __half22float2(h3);
            rs0 += (f0.x + f0.y) + (f2.x + f2.y);
            rs1 += (f1.x + f1.y) + (f3.x + f3.y);
        }

        // ---- GEMM-A: O += P * (Vh + Vl) ----
        {
            const int brow  = (((lane >> 3) & 1) << 3) + (lane & 7);
            const int bcolb = (lane >> 4) << 3;
            #pragma unroll
            for (int kf = 0; kf < 4; ++kf) {
                uint32_t bv[8][2];
                #pragma unroll
                for (int j = 0; j < 4; ++j) {
                    uint32_t r4[4];
                    ldsm4t(r4, kbH + ((uint32_t)(((kf << 4) + brow) * SQ
                                                 + (j << 4) + bcolb) << 1));
                    bv[2*j][0] = r4[0]; bv[2*j][1] = r4[1];
                    bv[2*j+1][0] = r4[2]; bv[2*j+1][1] = r4[3];
                }
                #pragma unroll
                for (int nf = 0; nf < 8; ++nf) mma16816(oacc[nf], pa[kf], bv[nf]);
                #pragma unroll
                for (int j = 0; j < 4; ++j) {
                    uint32_t r4[4];
                    ldsm4t(r4, kbL + ((uint32_t)(((kf << 4) + brow) * SQ
                                                 + (j << 4) + bcolb) << 1));
                    bv[2*j][0] = r4[0]; bv[2*j][1] = r4[1];
                    bv[2*j+1][0] = r4[2]; bv[2*j+1][1] = r4[3];
                }
                #pragma unroll
                for (int nf = 0; nf < 8; ++nf) mma16816(oacc[nf], pa[kf], bv[nf]);
            }
        }
        if (++buf == 3) buf = 0;
    }

    // ---- finalize ----
    rs0 += __shfl_xor_sync(0xffffffffu, rs0, 1);
    rs0 += __shfl_xor_sync(0xffffffffu, rs0, 2);
    rs1 += __shfl_xor_sync(0xffffffffu, rs1, 1);
    rs1 += __shfl_xor_sync(0xffffffffu, rs1, 2);
    float inv0 = 1.f / rs0, inv1 = 1.f / rs1;

    if (LAYER == 1) {
        int h = bh & (H_ - 1);
        int b = bh >> 2;
        size_t rbase = ((size_t)b * N_ + grow0) * HD_ + h * D_;
        #pragma unroll
        for (int nf = 0; nf < 8; ++nf) {
            int c = (nf << 3) + (tg << 1);
            float b0v = bias[h * D_ + c], b1v = bias[h * D_ + c + 1];
            float2 v0, v1;
            v0.x = lrelu(fmaf(oacc[nf][0], inv0, b0v));
            v0.y = lrelu(fmaf(oacc[nf][1], inv0, b1v));
            v1.x = lrelu(fmaf(oacc[nf][2], inv1, b0v));
            v1.y = lrelu(fmaf(oacc[nf][3], inv1, b1v));
            *(float2*)&g_z[rbase + c]           = v0;
            *(float2*)&g_z[rbase + 8 * HD_ + c] = v1;
        }
    } else {
        float v0[16], v1[16];
        float s0 = 0.f, s1 = 0.f;
        #pragma unroll
        for (int nf = 0; nf < 8; ++nf) {
            int c = (nf << 3) + (tg << 1);
            float b0v = bias[c], b1v = bias[c + 1];
            float a;
            a = lrelu(fmaf(oacc[nf][0], inv0, b0v)); v0[2*nf]   = a; s0 += a;
            a = lrelu(fmaf(oacc[nf][1], inv0, b1v)); v0[2*nf+1] = a; s0 += a;
            a = lrelu(fmaf(oacc[nf][2], inv1, b0v)); v1[2*nf]   = a; s1 += a;
            a = lrelu(fmaf(oacc[nf][3], inv1, b1v)); v1[2*nf+1] = a; s1 += a;
        }
        s0 += __shfl_xor_sync(0xffffffffu, s0, 1);
        s0 += __shfl_xor_sync(0xffffffffu, s0, 2);
        s1 += __shfl_xor_sync(0xffffffffu, s1, 1);
        s1 += __shfl_xor_sync(0xffffffffu, s1, 2);
        float mu0 = s0 * (1.f / 64.f), mu1 = s1 * (1.f / 64.f);
        float q0 = 0.f, q1 = 0.f;
        #pragma unroll
        for (int i = 0; i < 16; ++i) {
            float u0 = v0[i] - mu0; q0 += u0 * u0;
            float u1 = v1[i] - mu1; q1 += u1 * u1;
        }
        q0 += __shfl_xor_sync(0xffffffffu, q0, 1);
        q0 += __shfl_xor_sync(0xffffffffu, q0, 2);
        q1 += __shfl_xor_sync(0xffffffffu, q1, 1);
        q1 += __shfl_xor_sync(0xffffffffu, q1, 2);
        float rstd0 = rsqrtf(q0 * (1.f / 64.f) + 1e-5f);
        float rstd1 = rsqrtf(q1 * (1.f / 64.f) + 1e-5f);
        float* od0 = outp + ((size_t)bh * N_ + grow0) * D_;
        float* od1 = od0 + 8 * D_;
        #pragma unroll
        for (int nf = 0; nf < 8; ++nf) {
            int c = (nf << 3) + (tg << 1);
            float ga0 = gamma[c], ga1 = gamma[c + 1];
            float be0 = beta[c],  be1 = beta[c + 1];
            float2 w0, w1;
            w0.x = (v0[2*nf]   - mu0) * rstd0 * ga0 + be0;
            w0.y = (v0[2*nf+1] - mu0) * rstd0 * ga1 + be1;
            w1.x = (v1[2*nf]   - mu1) * rstd1 * ga0 + be0;
            w1.y = (v1[2*nf+1] - mu1) * rstd1 * ga1 + be1;
            *(float2*)&od0[c] = w0;
            *(float2*)&od1[c] = w1;
        }
    }
}

// ---------------- launch -----------------------------------------------------
extern "C" void kernel_launch(void* const* d_in, const int* in_sizes, int n_in,
                              void* d_out, int out_size) {
    const float* x     = (const float*)d_in[0];
    const int*   graph = (const int*)  d_in[1];
    const float* Wh    = (const float*)d_in[2];
    const float* bh    = (const float*)d_in[3];
    const float* Wo    = (const float*)d_in[4];
    const float* bo    = (const float*)d_in[5];
    const float* gamma = (const float*)d_in[6];
    const float* beta  = (const float*)d_in[7];
    float* out = (float*)d_out;

    cudaFuncSetAttribute(attn_mma<1>, cudaFuncAttributeMaxDynamicSharedMemorySize, SMEM_ATT);
    cudaFuncSetAttribute(attn_mma<2>, cudaFuncAttributeMaxDynamicSharedMemorySize, SMEM_ATT);

    build_mask_kernel<<<(N_ * NW_) / 8, 256>>>(graph);
    proj1_kernel<<<dim3(B_ * N_ / 64, H_), 256>>>(x, Wh);
    attn_mma<1><<<dim3(B_ * H_, N_ / 64), 128, SMEM_ATT>>>(bh, nullptr, nullptr, nullptr);
    proj2_kernel<<<(B_ * N_) / 64, 512>>>(Wo);
    attn_mma<2><<<dim3(B_, N_ / 64), 128, SMEM_ATT>>>(bo, gamma, beta, out);
}

// round 10
// speedup vs baseline: 14.5265x; 1.1858x over previous
#include <cuda_runtime.h>
#include <cuda_fp16.h>
#include <cstdint>

// Problem shape (fixed for this registry entry)
#define B_  8
#define N_  2048
#define C_  64
#define H_  4
#define D_  64
#define HD_ 256          // H*D
#define NW_ (N_/32)      // mask words per row = 64
#define LOG2E 1.4426950408889634f

// ---------------- scratch (device globals: no allocation allowed) -----------
__device__ __half  g_hH [B_*H_*N_*D_];    // layer1 features, f16 hi
__device__ __half  g_hL [B_*H_*N_*D_];    // layer1 features, f16 lo (residual)
__device__ __half  g_h2H[B_*N_*D_];       // layer2 features hi
__device__ __half  g_h2L[B_*N_*D_];       // layer2 features lo
__device__ float    g_z  [B_*N_*HD_];     // concat+lrelu of layer-1 output
__device__ unsigned g_maskT[NW_*N_];      // transposed bitmask [w][n]

__device__ __forceinline__ float ex2(float x) {
    float y;
    asm("ex2.approx.f32 %0, %1;" : "=f"(y) : "f"(x));
    return y;
}
__device__ __forceinline__ uint32_t smem_u32(const void* p) {
    uint32_t a;
    asm("{ .reg .u64 t; cvta.to.shared.u64 t, %1; cvt.u32.u64 %0, t; }" : "=r"(a) : "l"(p));
    return a;
}
__device__ __forceinline__ void cp16(uint32_t saddr, const void* g) {
    asm volatile("cp.async.ca.shared.global [%0], [%1], 16;"
                 :: "r"(saddr), "l"(__cvta_generic_to_global(g)));
}
__device__ __forceinline__ void ldsm4(uint32_t r[4], uint32_t addr) {
    asm volatile("ldmatrix.sync.aligned.m8n8.x4.shared.b16 {%0,%1,%2,%3}, [%4];"
                 : "=r"(r[0]), "=r"(r[1]), "=r"(r[2]), "=r"(r[3]) : "r"(addr));
}
__device__ __forceinline__ void ldsm4t(uint32_t r[4], uint32_t addr) {
    asm volatile("ldmatrix.sync.aligned.m8n8.x4.trans.shared.b16 {%0,%1,%2,%3}, [%4];"
                 : "=r"(r[0]), "=r"(r[1]), "=r"(r[2]), "=r"(r[3]) : "r"(addr));
}
__device__ __forceinline__ void mma16816(float d[4], const uint32_t a[4], const uint32_t b[2]) {
    asm volatile("mma.sync.aligned.m16n8k16.row.col.f32.f16.f16.f32 "
                 "{%0,%1,%2,%3}, {%4,%5,%6,%7}, {%8,%9}, {%0,%1,%2,%3};"
                 : "+f"(d[0]), "+f"(d[1]), "+f"(d[2]), "+f"(d[3])
                 : "r"(a[0]), "r"(a[1]), "r"(a[2]), "r"(a[3]), "r"(b[0]), "r"(b[1]));
}
__device__ __forceinline__ float lrelu(float a) { return a > 0.f ? a : 0.2f * a; }

__device__ __forceinline__ void split_store(__half* dH, __half* dL, size_t idx,
                                            float v0, float v1) {
    __half h0 = __float2half_rn(v0), h1 = __float2half_rn(v1);
    __half l0 = __float2half_rn(v0 - __half2float(h0));
    __half l1 = __float2half_rn(v1 - __half2float(h1));
    *(__half2*)&dH[idx] = __halves2half2(h0, h1);
    *(__half2*)&dL[idx] = __halves2half2(l0, l1);
}

// ---------------- mask build ------------------------------------------------
__global__ void build_mask_kernel(const int* __restrict__ graph) {
    int gwarp = (blockIdx.x * blockDim.x + threadIdx.x) >> 5;
    int lane  = threadIdx.x & 31;
    if (gwarp >= N_ * NW_) return;
    int n = gwarp >> 6;
    int w = gwarp & (NW_ - 1);
    int m = w * 32 + lane;
    bool bit = (graph[(size_t)n * N_ + m] != 0) || (m == n);
    unsigned word = __ballot_sync(0xffffffffu, bit);
    if (lane == 0) g_maskT[w * N_ + n] = word;
}

// ---------------- proj1: one head per blockIdx.y (grid 256 x 4) -------------
__global__ void proj1_kernel(const float* __restrict__ x,
                             const float* __restrict__ Wh) {
    __shared__ float xs[64][65];
    __shared__ float ws[64][65];
    int t    = threadIdx.x;              // 256 threads
    int row0 = blockIdx.x * 64;          // flattened b*N + n
    int h    = blockIdx.y;
    for (int i = t; i < 64 * 64; i += 256) {
        int r = i >> 6, c = i & 63;
        xs[r][c] = x[(size_t)(row0 + r) * C_ + c];
        ws[r][c] = Wh[((size_t)h * D_ + r) * C_ + c];
    }
    __syncthreads();
    int d0 = (t & 15) * 4;
    int r0 = (t >> 4) * 4;
    int b     = row0 >> 11;
    int nbase = row0 & (N_ - 1);
    float acc[4][4] = {};
    #pragma unroll 8
    for (int c = 0; c < 64; ++c) {
        float xv[4], wv[4];
        #pragma unroll
        for (int i = 0; i < 4; ++i) { xv[i] = xs[r0 + i][c]; wv[i] = ws[d0 + i][c]; }
        #pragma unroll
        for (int i = 0; i < 4; ++i)
            #pragma unroll
            for (int j = 0; j < 4; ++j)
                acc[i][j] += xv[i] * wv[j];
    }
    #pragma unroll
    for (int i = 0; i < 4; ++i) {
        size_t base = (((size_t)(b * H_ + h) * N_) + nbase + r0 + i) * D_ + d0;
        split_store(g_hH, g_hL, base,     acc[i][0], acc[i][1]);
        split_store(g_hH, g_hL, base + 2, acc[i][2], acc[i][3]);
    }
}

// ---------------- proj2: 256 threads, 4x4 micro-tile (R8 version) -----------
__global__ void proj2_kernel(const float* __restrict__ Wo) {
    __shared__ float zs[64][65];
    __shared__ float ws[64][65];
    int t    = threadIdx.x;
    int row0 = blockIdx.x * 64;
    int d0 = (t & 15) * 4;
    int r0 = (t >> 4) * 4;
    float acc[4][4] = {};
    for (int kc = 0; kc < 4; ++kc) {
        __syncthreads();
        for (int i = t; i < 64 * 64; i += 256) {
            int r = i >> 6, c = i & 63;
            zs[r][c] = g_z[(size_t)(row0 + r) * HD_ + kc * 64 + c];
            ws[r][c] = Wo[(size_t)r * HD_ + kc * 64 + c];
        }
        __syncthreads();
        #pragma unroll 8
        for (int c = 0; c < 64; ++c) {
            float xv[4], wv[4];
            #pragma unroll
            for (int i = 0; i < 4; ++i) { xv[i] = zs[r0 + i][c]; wv[i] = ws[d0 + i][c]; }
            #pragma unroll
            for (int i = 0; i < 4; ++i)
                #pragma unroll
                for (int j = 0; j < 4; ++j)
                    acc[i][j] += xv[i] * wv[j];
        }
    }
    #pragma unroll
    for (int i = 0; i < 4; ++i) {
        size_t base = (size_t)(row0 + r0 + i) * D_ + d0;
        split_store(g_h2H, g_h2L, base,     acc[i][0], acc[i][1]);
        split_store(g_h2H, g_h2L, base + 2, acc[i][2], acc[i][3]);
    }
}

// ================= HMMA flash attention, 4 warps / 64 rows ===================
// KV tile = 64 cols, 3-deep cp.async ring, 3 blocks/SM.
// S = QhKh + QhKl (2-term; QlKh dropped), P f16, O = P*Vh (Vl dropped).
#define SQ 72                          // smem row stride in halves
#define NT 32                          // KV tiles
#define SM_QH 0
#define SM_K  4608                     // ring starts after QH[64][72]
#define KBUF_HALVES 9216               // (KH + KL)[64][72]
#define SMEM_ATT ((4608 + 3 * KBUF_HALVES) * 2)   // 64512 bytes

template <int LAYER>
__global__ void __launch_bounds__(128, 3)
attn_mma(const float* __restrict__ bias,
         const float* __restrict__ gamma,
         const float* __restrict__ beta,
         float* __restrict__ outp) {
    extern __shared__ __half smh[];
    const int t    = threadIdx.x;
    const int wid  = t >> 5;            // 0..3
    const int lane = t & 31;
    const int g    = lane >> 2;
    const int tg   = lane & 3;
    const int wr0  = wid << 4;
    const int bh   = blockIdx.x;
    const int row0 = blockIdx.y << 6;   // 64 query rows per block
    const __half* hH = (LAYER == 1 ? g_hH : g_h2H) + (size_t)bh * (N_ * D_);
    const __half* hL = (LAYER == 1 ? g_hL : g_h2L) + (size_t)bh * (N_ * D_);
    const uint32_t sbase = smem_u32(smh);

    // ---- stage Q hi (64 rows) via plain loads ----
    {
        const uint4* sH = (const uint4*)(hH + (size_t)row0 * D_);
        #pragma unroll
        for (int i = 0; i < 4; ++i) {
            int idx = t + (i << 7);            // 0..511
            int r = idx >> 3, c8 = (idx & 7) << 3;
            *(uint4*)&smh[SM_QH + r * SQ + c8] = sH[idx];
        }
    }
    // ---- prefetch K tiles 0,1 into ring buffers 0,1 ----
    #pragma unroll
    for (int pt = 0; pt < 2; ++pt) {
        const uint4* sH = (const uint4*)(hH + (size_t)pt * (64 * D_));
        const uint4* sL = (const uint4*)(hL + (size_t)pt * (64 * D_));
        uint32_t kb = sbase + (uint32_t)(SM_K + pt * KBUF_HALVES) * 2;
        #pragma unroll
        for (int i = 0; i < 4; ++i) {
            int idx = t + (i << 7);            // 0..511
            int r = idx >> 3, c8 = (idx & 7) << 3;
            uint32_t so = (uint32_t)(r * SQ + c8) << 1;
            cp16(kb + so, sH + idx);
            cp16(kb + (4608u << 1) + so, sL + idx);
        }
        asm volatile("cp.async.commit_group;" ::: "memory");
    }
    __syncthreads();

    // ---- preload Q A-frags (hi only) ----
    uint32_t qh[4][4];
    {
        int arow  = wr0 + (lane & 15);
        int acolb = (lane >> 4) << 3;
        #pragma unroll
        for (int kf = 0; kf < 4; ++kf)
            ldsm4(qh[kf], sbase + ((uint32_t)(SM_QH + arow * SQ + (kf << 4) + acolb) << 1));
    }

    float oacc[8][4];
    #pragma unroll
    for (int i = 0; i < 8; ++i)
        #pragma unroll
        for (int j = 0; j < 4; ++j) oacc[i][j] = 0.f;
    float rs0 = 0.f, rs1 = 0.f, mr0 = -1e30f, mr1 = -1e30f;
    const int grow0 = row0 + wr0 + g;

    int buf = 0;
    #pragma unroll 1
    for (int tile = 0; tile < NT; ++tile) {
        asm volatile("cp.async.wait_group 1;" ::: "memory");
        __syncthreads();
        // ---- prefetch tile+2 into ring slot ----
        {
            int pt = tile + 2;
            if (pt < NT) {
                int pb = buf + 2; if (pb >= 3) pb -= 3;
                const uint4* sH = (const uint4*)(hH + (size_t)pt * (64 * D_));
                const uint4* sL = (const uint4*)(hL + (size_t)pt * (64 * D_));
                uint32_t kb = sbase + (uint32_t)(SM_K + pb * KBUF_HALVES) * 2;
                #pragma unroll
                for (int i = 0; i < 4; ++i) {
                    int idx = t + (i << 7);
                    int r = idx >> 3, c8 = (idx & 7) << 3;
                    uint32_t so = (uint32_t)(r * SQ + c8) << 1;
                    cp16(kb + so, sH + idx);
                    cp16(kb + (4608u << 1) + so, sL + idx);
                }
            }
            asm volatile("cp.async.commit_group;" ::: "memory");   // empty group ok
        }
        unsigned mw0[2], mw1[2];
        #pragma unroll
        for (int w = 0; w < 2; ++w) {
            mw0[w] = g_maskT[(size_t)((tile << 1) + w) * N_ + grow0];
            mw1[w] = g_maskT[(size_t)((tile << 1) + w) * N_ + grow0 + 8];
        }

        const uint32_t kbH = sbase + (uint32_t)(SM_K + buf * KBUF_HALVES) * 2;
        const uint32_t kbL = kbH + (4608u << 1);

        // ---- GEMM-S: sacc[8 nf][4], terms QhKh + QhKl ----
        float sacc[8][4];
        #pragma unroll
        for (int i = 0; i < 8; ++i)
            #pragma unroll
            for (int j = 0; j < 4; ++j) sacc[i][j] = 0.f;
        {
            const int brow = ((lane >> 4) << 3) + (lane & 7);
            const int bcol = ((lane >> 3) & 1) << 3;
            #pragma unroll
            for (int kf = 0; kf < 4; ++kf) {
                uint32_t bfr[8][2];
                #pragma unroll
                for (int j = 0; j < 4; ++j) {
                    uint32_t r4[4];
                    ldsm4(r4, kbH + ((uint32_t)(((j << 4) + brow) * SQ
                                                + (kf << 4) + bcol) << 1));
                    bfr[2*j][0] = r4[0]; bfr[2*j][1] = r4[1];
                    bfr[2*j+1][0] = r4[2]; bfr[2*j+1][1] = r4[3];
                }
                #pragma unroll
                for (int nf = 0; nf < 8; ++nf) mma16816(sacc[nf], qh[kf], bfr[nf]);
                #pragma unroll
                for (int j = 0; j < 4; ++j) {
                    uint32_t r4[4];
                    ldsm4(r4, kbL + ((uint32_t)(((j << 4) + brow) * SQ
                                                + (kf << 4) + bcol) << 1));
                    bfr[2*j][0] = r4[0]; bfr[2*j][1] = r4[1];
                    bfr[2*j+1][0] = r4[2]; bfr[2*j+1][1] = r4[3];
                }
                #pragma unroll
                for (int nf = 0; nf < 8; ++nf) mma16816(sacc[nf], qh[kf], bfr[nf]);
            }
        }

        // ---- masked online softmax; P -> A-frags in registers ----
        float m0 = -1e30f, m1 = -1e30f;
        #pragma unroll
        for (int nf = 0; nf < 8; ++nf) {
            unsigned w0 = mw0[nf >> 2], w1 = mw1[nf >> 2];
            int bb = ((nf & 3) << 3) + (tg << 1);
            m0 = fmaxf(m0, ((w0 >> bb) & 1u)       ? sacc[nf][0] : -1e30f);
            m0 = fmaxf(m0, ((w0 >> (bb + 1)) & 1u) ? sacc[nf][1] : -1e30f);
            m1 = fmaxf(m1, ((w1 >> bb) & 1u)       ? sacc[nf][2] : -1e30f);
            m1 = fmaxf(m1, ((w1 >> (bb + 1)) & 1u) ? sacc[nf][3] : -1e30f);
        }
        m0 = fmaxf(m0, __shfl_xor_sync(0xffffffffu, m0, 1));
        m0 = fmaxf(m0, __shfl_xor_sync(0xffffffffu, m0, 2));
        m1 = fmaxf(m1, __shfl_xor_sync(0xffffffffu, m1, 1));
        m1 = fmaxf(m1, __shfl_xor_sync(0xffffffffu, m1, 2));
        float mn0 = fmaxf(mr0, m0), mn1 = fmaxf(mr1, m1);
        float al0 = ex2((mr0 - mn0) * LOG2E), al1 = ex2((mr1 - mn1) * LOG2E);
        mr0 = mn0; mr1 = mn1;
        rs0 *= al0; rs1 *= al1;
        #pragma unroll
        for (int nf = 0; nf < 8; ++nf) {
            oacc[nf][0] *= al0; oacc[nf][1] *= al0;
            oacc[nf][2] *= al1; oacc[nf][3] *= al1;
        }
        const float mL0 = mn0 * LOG2E, mL1 = mn1 * LOG2E;
        uint32_t pa[4][4];
        #pragma unroll
        for (int k2 = 0; k2 < 4; ++k2) {
            int nfA = k2 << 1, nfB = nfA + 1;
            unsigned wA0 = mw0[nfA >> 2], wA1 = mw1[nfA >> 2];
            unsigned wB0 = mw0[nfB >> 2], wB1 = mw1[nfB >> 2];
            int bbA = ((nfA & 3) << 3) + (tg << 1);
            int bbB = ((nfB & 3) << 3) + (tg << 1);
            float p00 = ((wA0 >> bbA) & 1u)     ? ex2(fmaf(sacc[nfA][0], LOG2E, -mL0)) : 0.f;
            float p01 = ((wA0 >> (bbA+1)) & 1u) ? ex2(fmaf(sacc[nfA][1], LOG2E, -mL0)) : 0.f;
            float p02 = ((wA1 >> bbA) & 1u)     ? ex2(fmaf(sacc[nfA][2], LOG2E, -mL1)) : 0.f;
            float p03 = ((wA1 >> (bbA+1)) & 1u) ? ex2(fmaf(sacc[nfA][3], LOG2E, -mL1)) : 0.f;
            float p10 = ((wB0 >> bbB) & 1u)     ? ex2(fmaf(sacc[nfB][0], LOG2E, -mL0)) : 0.f;
            float p11 = ((wB0 >> (bbB+1)) & 1u) ? ex2(fmaf(sacc[nfB][1], LOG2E, -mL0)) : 0.f;
            float p12 = ((wB1 >> bbB) & 1u)     ? ex2(fmaf(sacc[nfB][2], LOG2E, -mL1)) : 0.f;
            float p13 = ((wB1 >> (bbB+1)) & 1u) ? ex2(fmaf(sacc[nfB][3], LOG2E, -mL1)) : 0.f;
            __half2 h0 = __floats2half2_rn(p00, p01);
            __half2 h1 = __floats2half2_rn(p02, p03);
            __half2 h2 = __floats2half2_rn(p10, p11);
            __half2 h3 = __floats2half2_rn(p12, p13);
            pa[k2][0] = *(uint32_t*)&h0; pa[k2][1] = *(uint32_t*)&h1;
            pa[k2][2] = *(uint32_t*)&h2; pa[k2][3] = *(uint32_t*)&h3;
            float2 f0 = __half22float2(h0), f2 = __half22float2(h2);
            float2 f1 = __half22float2(h1), f3 = __half22float2(h3);
            rs0 += (f0.x + f0.y) + (f2.x + f2.y);
            rs1 += (f1.x + f1.y) + (f3.x + f3.y);
        }

        // ---- GEMM-A: O += P * Vh (single term) ----
        {
            const int brow  = (((lane >> 3) & 1) << 3) + (lane & 7);
            const int bcolb = (lane >> 4) << 3;
            #pragma unroll
            for (int kf = 0; kf < 4; ++kf) {
                uint32_t bv[8][2];
                #pragma unroll
                for (int j = 0; j < 4; ++j) {
                    uint32_t r4[4];
                    ldsm4t(r4, kbH + ((uint32_t)(((kf << 4) + brow) * SQ
                                                 + (j << 4) + bcolb) << 1));
                    bv[2*j][0] = r4[0]; bv[2*j][1] = r4[1];
                    bv[2*j+1][0] = r4[2]; bv[2*j+1][1] = r4[3];
                }
                #pragma unroll
                for (int nf = 0; nf < 8; ++nf) mma16816(oacc[nf], pa[kf], bv[nf]);
            }
        }
        if (++buf == 3) buf = 0;
    }

    // ---- finalize ----
    rs0 += __shfl_xor_sync(0xffffffffu, rs0, 1);
    rs0 += __shfl_xor_sync(0xffffffffu, rs0, 2);
    rs1 += __shfl_xor_sync(0xffffffffu, rs1, 1);
    rs1 += __shfl_xor_sync(0xffffffffu, rs1, 2);
    float inv0 = 1.f / rs0, inv1 = 1.f / rs1;

    if (LAYER == 1) {
        int h = bh & (H_ - 1);
        int b = bh >> 2;
        size_t rbase = ((size_t)b * N_ + grow0) * HD_ + h * D_;
        #pragma unroll
        for (int nf = 0; nf < 8; ++nf) {
            int c = (nf << 3) + (tg << 1);
            float b0v = bias[h * D_ + c], b1v = bias[h * D_ + c + 1];
            float2 v0, v1;
            v0.x = lrelu(fmaf(oacc[nf][0], inv0, b0v));
            v0.y = lrelu(fmaf(oacc[nf][1], inv0, b1v));
            v1.x = lrelu(fmaf(oacc[nf][2], inv1, b0v));
            v1.y = lrelu(fmaf(oacc[nf][3], inv1, b1v));
            *(float2*)&g_z[rbase + c]           = v0;
            *(float2*)&g_z[rbase + 8 * HD_ + c] = v1;
        }
    } else {
        float v0[16], v1[16];
        float s0 = 0.f, s1 = 0.f;
        #pragma unroll
        for (int nf = 0; nf < 8; ++nf) {
            int c = (nf << 3) + (tg << 1);
            float b0v = bias[c], b1v = bias[c + 1];
            float a;
            a = lrelu(fmaf(oacc[nf][0], inv0, b0v)); v0[2*nf]   = a; s0 += a;
            a = lrelu(fmaf(oacc[nf][1], inv0, b1v)); v0[2*nf+1] = a; s0 += a;
            a = lrelu(fmaf(oacc[nf][2], inv1, b0v)); v1[2*nf]   = a; s1 += a;
            a = lrelu(fmaf(oacc[nf][3], inv1, b1v)); v1[2*nf+1] = a; s1 += a;
        }
        s0 += __shfl_xor_sync(0xffffffffu, s0, 1);
        s0 += __shfl_xor_sync(0xffffffffu, s0, 2);
        s1 += __shfl_xor_sync(0xffffffffu, s1, 1);
        s1 += __shfl_xor_sync(0xffffffffu, s1, 2);
        float mu0 = s0 * (1.f / 64.f), mu1 = s1 * (1.f / 64.f);
        float q0 = 0.f, q1 = 0.f;
        #pragma unroll
        for (int i = 0; i < 16; ++i) {
            float u0 = v0[i] - mu0; q0 += u0 * u0;
            float u1 = v1[i] - mu1; q1 += u1 * u1;
        }
        q0 += __shfl_xor_sync(0xffffffffu, q0, 1);
        q0 += __shfl_xor_sync(0xffffffffu, q0, 2);
        q1 += __shfl_xor_sync(0xffffffffu, q1, 1);
        q1 += __shfl_xor_sync(0xffffffffu, q1, 2);
        float rstd0 = rsqrtf(q0 * (1.f / 64.f) + 1e-5f);
        float rstd1 = rsqrtf(q1 * (1.f / 64.f) + 1e-5f);
        float* od0 = outp + ((size_t)bh * N_ + grow0) * D_;
        float* od1 = od0 + 8 * D_;
        #pragma unroll
        for (int nf = 0; nf < 8; ++nf) {
            int c = (nf << 3) + (tg << 1);
            float ga0 = gamma[c], ga1 = gamma[c + 1];
            float be0 = beta[c],  be1 = beta[c + 1];
            float2 w0, w1;
            w0.x = (v0[2*nf]   - mu0) * rstd0 * ga0 + be0;
            w0.y = (v0[2*nf+1] - mu0) * rstd0 * ga1 + be1;
            w1.x = (v1[2*nf]   - mu1) * rstd1 * ga0 + be0;
            w1.y = (v1[2*nf+1] - mu1) * rstd1 * ga1 + be1;
            *(float2*)&od0[c] = w0;
            *(float2*)&od1[c] = w1;
        }
    }
}

// ---------------- launch -----------------------------------------------------
extern "C" void kernel_launch(void* const* d_in, const int* in_sizes, int n_in,
                              void* d_out, int out_size) {
    const float* x     = (const float*)d_in[0];
    const int*   graph = (const int*)  d_in[1];
    const float* Wh    = (const float*)d_in[2];
    const float* bh    = (const float*)d_in[3];
    const float* Wo    = (const float*)d_in[4];
    const float* bo    = (const float*)d_in[5];
    const float* gamma = (const float*)d_in[6];
    const float* beta  = (const float*)d_in[7];
    float* out = (float*)d_out;

    cudaFuncSetAttribute(attn_mma<1>, cudaFuncAttributeMaxDynamicSharedMemorySize, SMEM_ATT);
    cudaFuncSetAttribute(attn_mma<2>, cudaFuncAttributeMaxDynamicSharedMemorySize, SMEM_ATT);

    build_mask_kernel<<<(N_ * NW_) / 8, 256>>>(graph);
    proj1_kernel<<<dim3(B_ * N_ / 64, H_), 256>>>(x, Wh);
    attn_mma<1><<<dim3(B_ * H_, N_ / 64), 128, SMEM_ATT>>>(bh, nullptr, nullptr, nullptr);
    proj2_kernel<<<(B_ * N_) / 64, 256>>>(Wo);
    attn_mma<2><<<dim3(B_, N_ / 64), 128, SMEM_ATT>>>(bo, gamma, beta, out);
}